// round 12
// baseline (speedup 1.0000x reference)
#include <cuda_runtime.h>
#include <math.h>
#include <stdint.h>

// ---------------- problem constants ----------------
#define T_TOK   2048
#define DM      1024
#define HM      512
#define ER      64
#define TOPK    6
#define ES      2
#define NGRP    (ER + ES)
#define NPAIR_R (T_TOK * TOPK)
#define NPAIR   (NPAIR_R + T_TOK * ES)
#define EPSR    1.1920929e-07f

// ---------------- GEMM tile config ----------------
#define BMG   256                 // block M
#define BNG   128                 // block N
#define BK    64                  // block K
#define AST   36                  // uint32 stride per A row (32 data + 4 pad)
#define BST   68                  // uint32 stride per B k-row (64 data + 4 pad)
#define ABUF_BYTES (BMG * AST * 4)  // 36864
#define BBUF_BYTES (BK * BST * 4)   // 17408
#define BBUFW (BK * BST)
#define BOFF  (3 * ABUF_BYTES)      // 110592 (A triple-buffered)
#define XOFF  (BOFF + 2 * BBUF_BYTES) // 145408
#define DSMEM (XOFF + 2048)         // 147456 bytes dynamic smem

// ---------------- device scratch ----------------
__device__ float    g_xn [T_TOK * DM];
__device__ uint32_t g_xnb[T_TOK * DM / 2];
__device__ int      g_idx[T_TOK * TOPK];
__device__ float    g_wk [T_TOK * TOPK];
__device__ int      g_cnt[NGRP];
__device__ int      g_off[NGRP + 1];
__device__ int      g_fill[ER];
__device__ int      g_ptok[NPAIR];
__device__ float    g_pw  [NPAIR];
__device__ int      g_pos [T_TOK * 8];
__device__ uint32_t g_hb  [(size_t)NPAIR * HM / 2];
__device__ uint32_t g_gb  [(size_t)NPAIR * HM / 2];
__device__ float    g_po  [(size_t)NPAIR * DM];

// ---------------- PTX helpers ----------------
__device__ __forceinline__ uint32_t pk(float lo, float hi) {
    uint32_t r;
    asm("cvt.rn.bf16x2.f32 %0, %1, %2;" : "=r"(r) : "f"(hi), "f"(lo));
    return r;
}
__device__ __forceinline__ uint32_t cvta(const void* p) {
    return (uint32_t)__cvta_generic_to_shared(p);
}
__device__ __forceinline__ void mma_bf16(float* c, uint32_t a0, uint32_t a1,
                                         uint32_t a2, uint32_t a3,
                                         uint32_t b0, uint32_t b1) {
    asm volatile(
        "mma.sync.aligned.m16n8k16.row.col.f32.bf16.bf16.f32 "
        "{%0,%1,%2,%3}, {%4,%5,%6,%7}, {%8,%9}, {%0,%1,%2,%3};\n"
        : "+f"(c[0]), "+f"(c[1]), "+f"(c[2]), "+f"(c[3])
        : "r"(a0), "r"(a1), "r"(a2), "r"(a3), "r"(b0), "r"(b1));
}
__device__ __forceinline__ void ldsm4(uint32_t& r0, uint32_t& r1, uint32_t& r2,
                                      uint32_t& r3, uint32_t a) {
    asm volatile("ldmatrix.sync.aligned.m8n8.x4.shared.b16 {%0,%1,%2,%3}, [%4];"
                 : "=r"(r0), "=r"(r1), "=r"(r2), "=r"(r3) : "r"(a));
}
__device__ __forceinline__ void ldsm4t(uint32_t& r0, uint32_t& r1, uint32_t& r2,
                                       uint32_t& r3, uint32_t a) {
    asm volatile("ldmatrix.sync.aligned.m8n8.x4.trans.shared.b16 {%0,%1,%2,%3}, [%4];"
                 : "=r"(r0), "=r"(r1), "=r"(r2), "=r"(r3) : "r"(a));
}
// .ca: KEEP L1 caching (round-10 .cg experiment regressed 131->235us)
#define CPA(dst, src) \
    asm volatile("cp.async.ca.shared.global [%0], [%1], 16;" \
                 :: "r"(dst), "l"(src) : "memory")
#define CPC()  asm volatile("cp.async.commit_group;" ::: "memory")
#define CPW0() asm volatile("cp.async.wait_group 0;" ::: "memory")
#define CPW1() asm volatile("cp.async.wait_group 1;" ::: "memory")
#define CPA4(dstv, srcv) do { \
    uint32_t _d = (dstv); const uint32_t* _s = (srcv); \
    CPA(_d, _s); CPA(_d + 16, _s + 4); CPA(_d + 32, _s + 8); CPA(_d + 48, _s + 12); \
} while (0)

// ---------------- kernel 1: RMSNorm + residual init (+counter reset) --------
__global__ void __launch_bounds__(256) k_rmsnorm(const float* __restrict__ x,
                                                 const float* __restrict__ nw,
                                                 float* __restrict__ out) {
    int t = blockIdx.x, tid = threadIdx.x;
    if (blockIdx.x == 0) {
        if (tid < NGRP) g_cnt[tid] = (tid < ER) ? 0 : T_TOK;
        if (tid >= 128 && tid < 128 + ER) g_fill[tid - 128] = 0;
    }
    const float4* xr = (const float4*)(x + (size_t)t * DM);
    float4 a = xr[tid];
    float s = a.x * a.x + a.y * a.y + a.z * a.z + a.w * a.w;
    #pragma unroll
    for (int o = 16; o; o >>= 1) s += __shfl_xor_sync(0xffffffffu, s, o);
    __shared__ float ws[8];
    __shared__ float s_scale;
    if ((tid & 31) == 0) ws[tid >> 5] = s;
    __syncthreads();
    if (tid == 0) {
        float tot = 0.f;
        #pragma unroll
        for (int i = 0; i < 8; i++) tot += ws[i];
        s_scale = rsqrtf(tot / (float)DM + EPSR);
    }
    __syncthreads();
    float sc = s_scale;
    float4 w4 = ((const float4*)nw)[tid];
    float4 r;
    r.x = a.x * sc * w4.x; r.y = a.y * sc * w4.y;
    r.z = a.z * sc * w4.z; r.w = a.w * sc * w4.w;
    ((float4*)g_xn)[(size_t)t * 256 + tid] = r;
    ((uint2*)g_xnb)[(size_t)t * 256 + tid] = make_uint2(pk(r.x, r.y), pk(r.z, r.w));
    ((float4*)out)[(size_t)t * 256 + tid]  = a;
}

// ---------------- kernel 2: router (raw affinities fp32 + top-6 fused) ------
#define RPAD 68
__global__ void __launch_bounds__(256) k_route(const float* __restrict__ Wr,
                                               const float* __restrict__ bias) {
    __shared__ float As[16][RPAD];
    __shared__ float Bs[16][RPAD];
    __shared__ float sraw[64][65];
    int t0 = blockIdx.x * 64;
    int tid = threadIdx.x, tx = tid & 15, ty = tid >> 4;
    float acc[4][4];
    #pragma unroll
    for (int i = 0; i < 4; i++)
        #pragma unroll
        for (int j = 0; j < 4; j++) acc[i][j] = 0.f;
    int m = tid >> 2, kv = tid & 3;
    for (int kk = 0; kk < DM; kk += 16) {
        float4 av = *(const float4*)(g_xn + (size_t)(t0 + m) * DM + kk + kv * 4);
        float4 bv = *(const float4*)(Wr + (size_t)m * DM + kk + kv * 4);
        As[kv * 4 + 0][m] = av.x; As[kv * 4 + 1][m] = av.y;
        As[kv * 4 + 2][m] = av.z; As[kv * 4 + 3][m] = av.w;
        Bs[kv * 4 + 0][m] = bv.x; Bs[kv * 4 + 1][m] = bv.y;
        Bs[kv * 4 + 2][m] = bv.z; Bs[kv * 4 + 3][m] = bv.w;
        __syncthreads();
        #pragma unroll
        for (int k = 0; k < 16; k++) {
            float4 a4 = *(float4*)&As[k][ty * 4];
            float4 b4 = *(float4*)&Bs[k][tx * 4];
            float aa[4] = {a4.x, a4.y, a4.z, a4.w};
            float bb[4] = {b4.x, b4.y, b4.z, b4.w};
            #pragma unroll
            for (int i = 0; i < 4; i++)
                #pragma unroll
                for (int j = 0; j < 4; j++) acc[i][j] += aa[i] * bb[j];
        }
        __syncthreads();
    }
    #pragma unroll
    for (int i = 0; i < 4; i++)
        #pragma unroll
        for (int j = 0; j < 4; j++)
            sraw[ty * 4 + i][tx * 4 + j] = acc[i][j];
    __syncthreads();
    int lane = tid & 31, wid = tid >> 5;
    float b0 = bias[lane], b1 = bias[lane + 32];
    #pragma unroll
    for (int q = 0; q < 8; q++) {
        int lt = wid * 8 + q;
        int t = t0 + lt;
        float r0 = sraw[lt][lane];
        float r1 = sraw[lt][lane + 32];
        float a0 = r0 + b0;
        float a1 = r1 + b1;
        float sum = 0.f;
        int   sel_e[TOPK];
        float sel_r[TOPK];
        #pragma unroll
        for (int k = 0; k < TOPK; k++) {
            float v; int e;
            if (a0 >= a1) { v = a0; e = lane; } else { v = a1; e = lane + 32; }
            #pragma unroll
            for (int o = 16; o; o >>= 1) {
                float ov = __shfl_xor_sync(0xffffffffu, v, o);
                int   oe = __shfl_xor_sync(0xffffffffu, e, o);
                if (ov > v || (ov == v && oe < e)) { v = ov; e = oe; }
            }
            if (e == lane)      a0 = -1e30f;
            if (e == lane + 32) a1 = -1e30f;
            float ra = __shfl_sync(0xffffffffu, r0, e & 31);
            float rb = __shfl_sync(0xffffffffu, r1, e & 31);
            float rs = (e < 32) ? ra : rb;
            sel_e[k] = e; sel_r[k] = rs; sum += rs;
        }
        float inv = 1.f / sum;
        if (lane < TOPK) {
            g_idx[t * TOPK + lane] = sel_e[lane];
            g_wk [t * TOPK + lane] = sel_r[lane] * inv;
            atomicAdd(&g_cnt[sel_e[lane]], 1);
        }
    }
}

// ---------------- kernel 3: scatter (fused per-block scan) ----------------
__global__ void __launch_bounds__(256) k_scatter() {
    __shared__ int s_off[NGRP + 1];
    int tid = threadIdx.x;
    if (tid == 0) {
        int acc = 0;
        #pragma unroll
        for (int i = 0; i < NGRP; i++) { s_off[i] = acc; acc += g_cnt[i]; }
        s_off[NGRP] = acc;
    }
    __syncthreads();
    if (blockIdx.x == 0 && tid <= NGRP) g_off[tid] = s_off[tid];
    int p = blockIdx.x * 256 + tid;
    if (p >= NPAIR) return;
    if (p < NPAIR_R) {
        int t = p / TOPK, k = p % TOPK;
        int e = g_idx[p];
        int pos = s_off[e] + atomicAdd(&g_fill[e], 1);
        g_ptok[pos] = t;
        g_pw  [pos] = g_wk[p];
        g_pos[t * 8 + k] = pos;
    } else {
        int q = p - NPAIR_R;
        int j = q / T_TOK, t = q % T_TOK;
        int pos = s_off[ER + j] + t;
        g_ptok[pos] = t;
        g_pw  [pos] = 1.0f;
        g_pos[t * 8 + TOPK + j] = pos;
    }
}

// ================= GEMM core: BM=256, BN=128, BK=64, 512 thr ================
// 16 warps as 8m x 2n, warp tile 32x64 (2 m16 x 8 n8)
__device__ __forceinline__ void mma_chunk(uint32_t aA, uint32_t aB,
                                          float acc[2][8][4],
                                          int warp_m, int warp_n, int lane) {
    int sel = lane >> 3, li = lane & 7;
    int arow = (sel & 1) * 8 + li;
    int acol = (sel >> 1) * 4;
    int brow = (sel & 1) * 8 + li;
    int bn   = (sel >> 1) * 8;
    #pragma unroll
    for (int ks = 0; ks < 4; ks++) {
        uint32_t a[2][4];
        #pragma unroll
        for (int s = 0; s < 2; s++) {
            uint32_t addr = aA + (uint32_t)(((warp_m * 32 + s * 16 + arow) * AST
                                             + ks * 8 + acol) * 4);
            ldsm4(a[s][0], a[s][1], a[s][2], a[s][3], addr);
        }
        #pragma unroll
        for (int p = 0; p < 4; p++) {
            uint32_t b0, b1, b2, b3;
            uint32_t addr = aB + (uint32_t)((ks * 16 + brow) * (BST * 4)
                                            + (warp_n * 64 + p * 16 + bn) * 2);
            ldsm4t(b0, b1, b2, b3, addr);
            #pragma unroll
            for (int s = 0; s < 2; s++) {
                mma_bf16(acc[s][2 * p],     a[s][0], a[s][1], a[s][2], a[s][3], b0, b1);
                mma_bf16(acc[s][2 * p + 1], a[s][0], a[s][1], a[s][2], a[s][3], b2, b3);
            }
        }
    }
}

// B chunk: 64 k-rows x 128 n fp32 -> 16 regs (512 threads)
__device__ __forceinline__ void ldB(const float* __restrict__ W, int ldb, int kk,
                                    int nb, int tid, float4 f[4]) {
    const float* p = W + (size_t)(kk + (tid >> 3)) * ldb + nb + (tid & 7) * 16;
    f[0] = *(const float4*)p;
    f[1] = *(const float4*)(p + 4);
    f[2] = *(const float4*)(p + 8);
    f[3] = *(const float4*)(p + 12);
}
__device__ __forceinline__ void stB(uint32_t* Bbase, int tid, const float4 f[4]) {
    uint32_t* d = Bbase + (tid >> 3) * BST + (tid & 7) * 8;
    *(uint4*)d = make_uint4(pk(f[0].x, f[0].y), pk(f[0].z, f[0].w),
                            pk(f[1].x, f[1].y), pk(f[1].z, f[1].w));
    *(uint4*)(d + 4) = make_uint4(pk(f[2].x, f[2].y), pk(f[2].z, f[2].w),
                                  pk(f[3].x, f[3].y), pk(f[3].z, f[3].w));
}

// ---------------- kernel 4: grouped GEMM1 h = gather(xnb) @ W1[e] + b1 ------
__global__ void __launch_bounds__(512, 1)
k_gemm1(const float* __restrict__ rW1, const float* __restrict__ sW1,
        const float* __restrict__ rb1, const float* __restrict__ sb1) {
    extern __shared__ uint8_t dyn[];
    uint32_t* Bb = (uint32_t*)(dyn + BOFF);
    const uint32_t** sArow = (const uint32_t**)(dyn + XOFF);
    uint32_t saA = cvta(dyn), saB = cvta(Bb);
    int grp = blockIdx.z;
    int start = g_off[grp], cnt = g_off[grp + 1] - start;
    if ((int)blockIdx.x * BMG >= cnt) return;
    const float* W  = (grp < ER) ? rW1 + (size_t)grp * DM * HM
                                 : sW1 + (size_t)(grp - ER) * DM * HM;
    const float* bv = (grp < ER) ? rb1 + (size_t)grp * HM
                                 : sb1 + (size_t)(grp - ER) * HM;
    int nb = blockIdx.y * BNG;
    int tid = threadIdx.x, lane = tid & 31, wid = tid >> 5;
    int warp_m = wid >> 1, warp_n = wid & 1;
    int amf = tid >> 1, ahalf = (tid & 1) * 16;
    uint32_t aoff = (uint32_t)((amf * AST + ahalf) * 4);
    const int nch = DM / BK;   // 16

    for (int mt = blockIdx.x; mt * BMG < cnt; mt += gridDim.x) {
        int m0 = mt * BMG;
        int rem = cnt - m0; if (rem > BMG) rem = BMG;
        bool active = (warp_m * 32 < rem);
        __syncthreads();
        if (tid < BMG)
            sArow[tid] = (tid < rem)
                ? g_xnb + (size_t)g_ptok[start + m0 + tid] * (DM / 2) : g_xnb;
        __syncthreads();
        float acc[2][8][4];
        #pragma unroll
        for (int s = 0; s < 2; s++)
            #pragma unroll
            for (int n = 0; n < 8; n++)
                #pragma unroll
                for (int j = 0; j < 4; j++) acc[s][n][j] = 0.f;
        // prologue: B(0), A(0), A(1)
        {
            float4 f[4];
            ldB(W, HM, 0, nb, tid, f);
            stB(Bb, tid, f);
            CPA4(saA + aoff, sArow[amf] + ahalf); CPC();
            CPA4(saA + ABUF_BYTES + aoff, sArow[amf] + 32 + ahalf); CPC();
            CPW1();   // A(0) landed, A(1) in flight
        }
        __syncthreads();
        int abuf = 0;
        for (int c = 0; c < nch; c++) {
            float4 f[4];
            bool pre1 = (c + 1 < nch), pre2 = (c + 2 < nch);
            if (pre2) {
                int nbuf = abuf + 2; if (nbuf >= 3) nbuf -= 3;
                CPA4(saA + (uint32_t)nbuf * ABUF_BYTES + aoff,
                     sArow[amf] + (c + 2) * 32 + ahalf);
                CPC();
            }
            if (pre1) ldB(W, HM, (c + 1) * BK, nb, tid, f);
            if (active)
                mma_chunk(saA + (uint32_t)abuf * ABUF_BYTES,
                          saB + (c & 1) * BBUF_BYTES, acc, warp_m, warp_n, lane);
            if (pre1) stB(Bb + ((c + 1) & 1) * BBUFW, tid, f);
            if (pre2) { CPW1(); } else if (pre1) { CPW0(); }
            __syncthreads();
            abuf++; if (abuf == 3) abuf = 0;
        }
        if (active) {
            #pragma unroll
            for (int s = 0; s < 2; s++) {
                int mrow = warp_m * 32 + s * 16 + (lane >> 2);
                #pragma unroll
                for (int nt = 0; nt < 8; nt++) {
                    int col = nb + warp_n * 64 + nt * 8 + (lane & 3) * 2;
                    float2 bb = *(const float2*)&bv[col];
                    if (mrow < rem) {
                        size_t p = (size_t)(start + m0 + mrow);
                        g_hb[(p * HM + col) >> 1] =
                            pk(acc[s][nt][0] + bb.x, acc[s][nt][1] + bb.y);
                    }
                    if (mrow + 8 < rem) {
                        size_t p = (size_t)(start + m0 + mrow + 8);
                        g_hb[(p * HM + col) >> 1] =
                            pk(acc[s][nt][2] + bb.x, acc[s][nt][3] + bb.y);
                    }
                }
            }
        }
    }
}

// ---------------- kernel 5: gate  g = silu(h @ Wg) * h ----------------
__global__ void __launch_bounds__(512, 1)
k_gate(const float* __restrict__ rWg, const float* __restrict__ sWg) {
    extern __shared__ uint8_t dyn[];
    uint32_t* Bb = (uint32_t*)(dyn + BOFF);
    uint32_t saA = cvta(dyn), saB = cvta(Bb);
    int p0 = blockIdx.x * BMG;
    const float* W = (p0 < NPAIR_R) ? rWg : sWg;
    int nb = blockIdx.y * BNG;
    int tid = threadIdx.x, lane = tid & 31, wid = tid >> 5;
    int warp_m = wid >> 1, warp_n = wid & 1;
    int amf = tid >> 1, ahalf = (tid & 1) * 16;
    uint32_t aoff = (uint32_t)((amf * AST + ahalf) * 4);
    const uint32_t* arow = g_hb + (size_t)(p0 + amf) * (HM / 2);
    const int nch = HM / BK;   // 8

    float acc[2][8][4];
    #pragma unroll
    for (int s = 0; s < 2; s++)
        #pragma unroll
        for (int n = 0; n < 8; n++)
            #pragma unroll
            for (int j = 0; j < 4; j++) acc[s][n][j] = 0.f;
    {
        float4 f[4];
        ldB(W, HM, 0, nb, tid, f);
        stB(Bb, tid, f);
        CPA4(saA + aoff, arow + ahalf); CPC();
        CPA4(saA + ABUF_BYTES + aoff, arow + 32 + ahalf); CPC();
        CPW1();
    }
    __syncthreads();
    int abuf = 0;
    for (int c = 0; c < nch; c++) {
        float4 f[4];
        bool pre1 = (c + 1 < nch), pre2 = (c + 2 < nch);
        if (pre2) {
            int nbuf = abuf + 2; if (nbuf >= 3) nbuf -= 3;
            CPA4(saA + (uint32_t)nbuf * ABUF_BYTES + aoff,
                 arow + (c + 2) * 32 + ahalf);
            CPC();
        }
        if (pre1) ldB(W, HM, (c + 1) * BK, nb, tid, f);
        mma_chunk(saA + (uint32_t)abuf * ABUF_BYTES,
                  saB + (c & 1) * BBUF_BYTES, acc, warp_m, warp_n, lane);
        if (pre1) stB(Bb + ((c + 1) & 1) * BBUFW, tid, f);
        if (pre2) { CPW1(); } else if (pre1) { CPW0(); }
        __syncthreads();
        abuf++; if (abuf == 3) abuf = 0;
    }
    #pragma unroll
    for (int s = 0; s < 2; s++) {
        int mrow = warp_m * 32 + s * 16 + (lane >> 2);
        #pragma unroll
        for (int nt = 0; nt < 8; nt++) {
            int col = nb + warp_n * 64 + nt * 8 + (lane & 3) * 2;
            #pragma unroll
            for (int hh = 0; hh < 2; hh++) {
                size_t p = (size_t)(p0 + mrow + hh * 8);
                size_t idx = (p * HM + col) >> 1;
                uint32_t hu = g_hb[idx];
                float h0 = __uint_as_float(hu << 16);
                float h1 = __uint_as_float(hu & 0xffff0000u);
                float v0 = acc[s][nt][hh * 2 + 0];
                float v1 = acc[s][nt][hh * 2 + 1];
                float r0 = (v0 / (1.f + __expf(-v0))) * h0;
                float r1 = (v1 / (1.f + __expf(-v1))) * h1;
                g_gb[idx] = pk(r0, r1);
            }
        }
    }
}

// ---------------- kernel 6: grouped GEMM2 po = (g @ W2[e] + b2) * w ----------
__global__ void __launch_bounds__(512, 1)
k_gemm2(const float* __restrict__ rW2, const float* __restrict__ sW2,
        const float* __restrict__ rb2, const float* __restrict__ sb2) {
    extern __shared__ uint8_t dyn[];
    uint32_t* Bb = (uint32_t*)(dyn + BOFF);
    float* sPw = (float*)(dyn + XOFF);
    uint32_t saA = cvta(dyn), saB = cvta(Bb);
    int grp = blockIdx.z;
    int start = g_off[grp], cnt = g_off[grp + 1] - start;
    if ((int)blockIdx.x * BMG >= cnt) return;
    const float* W  = (grp < ER) ? rW2 + (size_t)grp * HM * DM
                                 : sW2 + (size_t)(grp - ER) * HM * DM;
    const float* bv = (grp < ER) ? rb2 + (size_t)grp * DM
                                 : sb2 + (size_t)(grp - ER) * DM;
    int nb = blockIdx.y * BNG;
    int tid = threadIdx.x, lane = tid & 31, wid = tid >> 5;
    int warp_m = wid >> 1, warp_n = wid & 1;
    int amf = tid >> 1, ahalf = (tid & 1) * 16;
    uint32_t aoff = (uint32_t)((amf * AST + ahalf) * 4);
    const int nch = HM / BK;   // 8

    for (int mt = blockIdx.x; mt * BMG < cnt; mt += gridDim.x) {
        int m0 = mt * BMG;
        int rem = cnt - m0; if (rem > BMG) rem = BMG;
        bool active = (warp_m * 32 < rem);
        __syncthreads();
        if (tid < BMG) sPw[tid] = (tid < rem) ? g_pw[start + m0 + tid] : 0.f;
        __syncthreads();
        int ar = amf < rem ? amf : (rem - 1);
        const uint32_t* arow = g_gb + (size_t)(start + m0 + ar) * (HM / 2);
        float acc[2][8][4];
        #pragma unroll
        for (int s = 0; s < 2; s++)
            #pragma unroll
            for (int n = 0; n < 8; n++)
                #pragma unroll
                for (int j = 0; j < 4; j++) acc[s][n][j] = 0.f;
        {
            float4 f[4];
            ldB(W, DM, 0, nb, tid, f);
            stB(Bb, tid, f);
            CPA4(saA + aoff, arow + ahalf); CPC();
            CPA4(saA + ABUF_BYTES + aoff, arow + 32 + ahalf); CPC();
            CPW1();
        }
        __syncthreads();
        int abuf = 0;
        for (int c = 0; c < nch; c++) {
            float4 f[4];
            bool pre1 = (c + 1 < nch), pre2 = (c + 2 < nch);
            if (pre2) {
                int nbuf = abuf + 2; if (nbuf >= 3) nbuf -= 3;
                CPA4(saA + (uint32_t)nbuf * ABUF_BYTES + aoff,
                     arow + (c + 2) * 32 + ahalf);
                CPC();
            }
            if (pre1) ldB(W, DM, (c + 1) * BK, nb, tid, f);
            if (active)
                mma_chunk(saA + (uint32_t)abuf * ABUF_BYTES,
                          saB + (c & 1) * BBUF_BYTES, acc, warp_m, warp_n, lane);
            if (pre1) stB(Bb + ((c + 1) & 1) * BBUFW, tid, f);
            if (pre2) { CPW1(); } else if (pre1) { CPW0(); }
            __syncthreads();
            abuf++; if (abuf == 3) abuf = 0;
        }
        if (active) {
            #pragma unroll
            for (int s = 0; s < 2; s++) {
                int mrow = warp_m * 32 + s * 16 + (lane >> 2);
                #pragma unroll
                for (int nt = 0; nt < 8; nt++) {
                    int col = nb + warp_n * 64 + nt * 8 + (lane & 3) * 2;
                    float2 bb = *(const float2*)&bv[col];
                    if (mrow < rem) {
                        size_t p = (size_t)(start + m0 + mrow);
                        float w = sPw[mrow];
                        *(float2*)&g_po[p * DM + col] =
                            make_float2((acc[s][nt][0] + bb.x) * w,
                                        (acc[s][nt][1] + bb.y) * w);
                    }
                    if (mrow + 8 < rem) {
                        size_t p = (size_t)(start + m0 + mrow + 8);
                        float w = sPw[mrow + 8];
                        *(float2*)&g_po[p * DM + col] =
                            make_float2((acc[s][nt][2] + bb.x) * w,
                                        (acc[s][nt][3] + bb.y) * w);
                    }
                }
            }
        }
    }
}

// ---------------- kernel 7: per-token reduce of 8 pair rows ----------------
__global__ void __launch_bounds__(256) k_reduce(float* __restrict__ out) {
    int t = blockIdx.x, tid = threadIdx.x;
    __shared__ int pos[8];
    if (tid < 8) pos[tid] = g_pos[t * 8 + tid];
    __syncthreads();
    size_t d0 = (size_t)tid * 4;
    float4 s = *(float4*)&out[(size_t)t * DM + d0];
    #pragma unroll
    for (int j = 0; j < 8; j++) {
        float4 v = *(const float4*)&g_po[(size_t)pos[j] * DM + d0];
        s.x += v.x; s.y += v.y; s.z += v.z; s.w += v.w;
    }
    *(float4*)&out[(size_t)t * DM + d0] = s;
}

// ---------------- launcher ----------------
extern "C" void kernel_launch(void* const* d_in, const int* in_sizes, int n_in,
                              void* d_out, int out_size) {
    const float* x      = (const float*)d_in[0];
    const float* norm_w = (const float*)d_in[1];
    const float* Wr     = (const float*)d_in[2];
    const float* sW1    = (const float*)d_in[3];
    const float* sb1    = (const float*)d_in[4];
    const float* sW2    = (const float*)d_in[5];
    const float* sb2    = (const float*)d_in[6];
    const float* sWg    = (const float*)d_in[7];
    const float* rW1    = (const float*)d_in[8];
    const float* rb1    = (const float*)d_in[9];
    const float* rW2    = (const float*)d_in[10];
    const float* rb2    = (const float*)d_in[11];
    const float* rWg    = (const float*)d_in[12];
    const float* bias   = (const float*)d_in[13];
    float* out = (float*)d_out;

    cudaFuncSetAttribute(k_gemm1, cudaFuncAttributeMaxDynamicSharedMemorySize, DSMEM);
    cudaFuncSetAttribute(k_gate,  cudaFuncAttributeMaxDynamicSharedMemorySize, DSMEM);
    cudaFuncSetAttribute(k_gemm2, cudaFuncAttributeMaxDynamicSharedMemorySize, DSMEM);

    k_rmsnorm<<<T_TOK, 256>>>(x, norm_w, out);
    k_route<<<T_TOK / 64, 256>>>(Wr, bias);
    k_scatter<<<(NPAIR + 255) / 256, 256>>>();
    k_gemm1<<<dim3(8, HM / BNG, NGRP), 512, DSMEM>>>(rW1, sW1, rb1, sb1);
    k_gate<<<dim3(NPAIR / BMG, HM / BNG), 512, DSMEM>>>(rWg, sWg);
    k_gemm2<<<dim3(8, DM / BNG, NGRP), 512, DSMEM>>>(rW2, sW2, rb2, sb2);
    k_reduce<<<T_TOK, 256>>>(out);
}

// round 13
// speedup vs baseline: 1.4641x; 1.4641x over previous
#include <cuda_runtime.h>
#include <math.h>
#include <stdint.h>

// ---------------- problem constants ----------------
#define T_TOK   2048
#define DM      1024
#define HM      512
#define ER      64
#define TOPK    6
#define ES      2
#define NGRP    (ER + ES)
#define NPAIR_R (T_TOK * TOPK)
#define NPAIR   (NPAIR_R + T_TOK * ES)
#define EPSR    1.1920929e-07f

// ---------------- GEMM tile config (round-7 measured optimum) ----------------
#define BMG   256
#define BNG   128
#define BK    64
#define AST   36
#define BST   68
#define ABUF_BYTES (BMG * AST * 4)  // 36864
#define BBUF_BYTES (BK * BST * 4)   // 17408
#define BBUFW (BK * BST)
#define BOFF  (2 * ABUF_BYTES)      // 73728
#define XOFF  (BOFF + 2 * BBUF_BYTES) // 108544
#define DSMEM (XOFF + 2048)         // 110592

// ---------------- device scratch ----------------
__device__ float    g_xn [T_TOK * DM];
__device__ uint32_t g_xnb[T_TOK * DM / 2];
__device__ int      g_idx[T_TOK * TOPK];
__device__ float    g_wk [T_TOK * TOPK];
__device__ int      g_cnt[NGRP];
__device__ int      g_off[NGRP + 1];
__device__ int      g_fill[ER];
__device__ int      g_ptok[NPAIR];
__device__ float    g_pw  [NPAIR];
__device__ int      g_pos [T_TOK * 8];
__device__ uint32_t g_hb  [(size_t)NPAIR * HM / 2];
__device__ uint32_t g_gb  [(size_t)NPAIR * HM / 2];
__device__ float    g_po  [(size_t)NPAIR * DM];

// ---------------- PTX helpers ----------------
__device__ __forceinline__ uint32_t pk(float lo, float hi) {
    uint32_t r;
    asm("cvt.rn.bf16x2.f32 %0, %1, %2;" : "=r"(r) : "f"(hi), "f"(lo));
    return r;
}
__device__ __forceinline__ uint32_t cvta(const void* p) {
    return (uint32_t)__cvta_generic_to_shared(p);
}
__device__ __forceinline__ void mma_bf16(float* c, uint32_t a0, uint32_t a1,
                                         uint32_t a2, uint32_t a3,
                                         uint32_t b0, uint32_t b1) {
    asm volatile(
        "mma.sync.aligned.m16n8k16.row.col.f32.bf16.bf16.f32 "
        "{%0,%1,%2,%3}, {%4,%5,%6,%7}, {%8,%9}, {%0,%1,%2,%3};\n"
        : "+f"(c[0]), "+f"(c[1]), "+f"(c[2]), "+f"(c[3])
        : "r"(a0), "r"(a1), "r"(a2), "r"(a3), "r"(b0), "r"(b1));
}
__device__ __forceinline__ void ldsm4(uint32_t& r0, uint32_t& r1, uint32_t& r2,
                                      uint32_t& r3, uint32_t a) {
    asm volatile("ldmatrix.sync.aligned.m8n8.x4.shared.b16 {%0,%1,%2,%3}, [%4];"
                 : "=r"(r0), "=r"(r1), "=r"(r2), "=r"(r3) : "r"(a));
}
__device__ __forceinline__ void ldsm4t(uint32_t& r0, uint32_t& r1, uint32_t& r2,
                                       uint32_t& r3, uint32_t a) {
    asm volatile("ldmatrix.sync.aligned.m8n8.x4.trans.shared.b16 {%0,%1,%2,%3}, [%4];"
                 : "=r"(r0), "=r"(r1), "=r"(r2), "=r"(r3) : "r"(a));
}
// .ca: KEEP L1 caching (round-10 .cg regressed 131->235us; round-12 deeper
// pipeline regressed too — this double-buffered form is the measured optimum)
#define CPA(dst, src) \
    asm volatile("cp.async.ca.shared.global [%0], [%1], 16;" \
                 :: "r"(dst), "l"(src) : "memory")
#define CPC() asm volatile("cp.async.commit_group;" ::: "memory")
#define CPW() asm volatile("cp.async.wait_group 0;" ::: "memory")
#define CPA4(dstv, srcv) do { \
    uint32_t _d = (dstv); const uint32_t* _s = (srcv); \
    CPA(_d, _s); CPA(_d + 16, _s + 4); CPA(_d + 32, _s + 8); CPA(_d + 48, _s + 12); \
} while (0)

// ---------------- kernel 1: RMSNorm (+counter reset; residual added later) --
__global__ void __launch_bounds__(256) k_rmsnorm(const float* __restrict__ x,
                                                 const float* __restrict__ nw) {
    int t = blockIdx.x, tid = threadIdx.x;
    if (blockIdx.x == 0) {
        if (tid < NGRP) g_cnt[tid] = (tid < ER) ? 0 : T_TOK;
        if (tid >= 128 && tid < 128 + ER) g_fill[tid - 128] = 0;
    }
    const float4* xr = (const float4*)(x + (size_t)t * DM);
    float4 a = xr[tid];
    float s = a.x * a.x + a.y * a.y + a.z * a.z + a.w * a.w;
    #pragma unroll
    for (int o = 16; o; o >>= 1) s += __shfl_xor_sync(0xffffffffu, s, o);
    __shared__ float ws[8];
    __shared__ float s_scale;
    if ((tid & 31) == 0) ws[tid >> 5] = s;
    __syncthreads();
    if (tid == 0) {
        float tot = 0.f;
        #pragma unroll
        for (int i = 0; i < 8; i++) tot += ws[i];
        s_scale = rsqrtf(tot / (float)DM + EPSR);
    }
    __syncthreads();
    float sc = s_scale;
    float4 w4 = ((const float4*)nw)[tid];
    float4 r;
    r.x = a.x * sc * w4.x; r.y = a.y * sc * w4.y;
    r.z = a.z * sc * w4.z; r.w = a.w * sc * w4.w;
    ((float4*)g_xn)[(size_t)t * 256 + tid] = r;
    ((uint2*)g_xnb)[(size_t)t * 256 + tid] = make_uint2(pk(r.x, r.y), pk(r.z, r.w));
}

// ---------------- kernel 2: router — 16-token tiles (128 CTAs, full chip) ---
// M=16 tokens x N=64 experts x K=1024, BKr=32, fused top-6.
#define RT 16
__global__ void __launch_bounds__(256) k_route(const float* __restrict__ Wr,
                                               const float* __restrict__ bias) {
    __shared__ float As[32][17];     // [k][token]
    __shared__ float Bs[32][68];     // [k][expert]
    __shared__ float sraw[RT][68];
    int t0 = blockIdx.x * RT;
    int tid = threadIdx.x;
    int ty = tid >> 4, tx = tid & 15;      // token, expert-quad
    float acc[4] = {0.f, 0.f, 0.f, 0.f};
    int la_t = tid & 15, la_k = (tid >> 4) * 4;   // A loader (128 threads)
    int lb_e = tid & 63, lb_k = (tid >> 6) * 8;   // B loader (256 threads)
    for (int kk = 0; kk < DM; kk += 32) {
        if (tid < 128) {
            float4 v = *(const float4*)(g_xn + (size_t)(t0 + la_t) * DM + kk + la_k);
            As[la_k + 0][la_t] = v.x; As[la_k + 1][la_t] = v.y;
            As[la_k + 2][la_t] = v.z; As[la_k + 3][la_t] = v.w;
        }
        {
            const float* wp = Wr + (size_t)lb_e * DM + kk + lb_k;
            float4 v0 = *(const float4*)wp;
            float4 v1 = *(const float4*)(wp + 4);
            Bs[lb_k + 0][lb_e] = v0.x; Bs[lb_k + 1][lb_e] = v0.y;
            Bs[lb_k + 2][lb_e] = v0.z; Bs[lb_k + 3][lb_e] = v0.w;
            Bs[lb_k + 4][lb_e] = v1.x; Bs[lb_k + 5][lb_e] = v1.y;
            Bs[lb_k + 6][lb_e] = v1.z; Bs[lb_k + 7][lb_e] = v1.w;
        }
        __syncthreads();
        #pragma unroll
        for (int k = 0; k < 32; k++) {
            float a = As[k][ty];
            float4 b = *(const float4*)&Bs[k][tx * 4];
            acc[0] += a * b.x; acc[1] += a * b.y;
            acc[2] += a * b.z; acc[3] += a * b.w;
        }
        __syncthreads();
    }
    #pragma unroll
    for (int j = 0; j < 4; j++) sraw[ty][tx * 4 + j] = acc[j];
    __syncthreads();
    // ---- top-6: 8 warps x 2 tokens ----
    int lane = tid & 31, wid = tid >> 5;
    float b0 = bias[lane], b1 = bias[lane + 32];
    #pragma unroll
    for (int q = 0; q < 2; q++) {
        int lt = wid * 2 + q;
        int t = t0 + lt;
        float r0 = sraw[lt][lane];
        float r1 = sraw[lt][lane + 32];
        float a0 = r0 + b0;
        float a1 = r1 + b1;
        float sum = 0.f;
        int   sel_e[TOPK];
        float sel_r[TOPK];
        #pragma unroll
        for (int k = 0; k < TOPK; k++) {
            float v; int e;
            if (a0 >= a1) { v = a0; e = lane; } else { v = a1; e = lane + 32; }
            #pragma unroll
            for (int o = 16; o; o >>= 1) {
                float ov = __shfl_xor_sync(0xffffffffu, v, o);
                int   oe = __shfl_xor_sync(0xffffffffu, e, o);
                if (ov > v || (ov == v && oe < e)) { v = ov; e = oe; }
            }
            if (e == lane)      a0 = -1e30f;
            if (e == lane + 32) a1 = -1e30f;
            float ra = __shfl_sync(0xffffffffu, r0, e & 31);
            float rb = __shfl_sync(0xffffffffu, r1, e & 31);
            float rs = (e < 32) ? ra : rb;
            sel_e[k] = e; sel_r[k] = rs; sum += rs;
        }
        float inv = 1.f / sum;
        if (lane < TOPK) {
            g_idx[t * TOPK + lane] = sel_e[lane];
            g_wk [t * TOPK + lane] = sel_r[lane] * inv;
            atomicAdd(&g_cnt[sel_e[lane]], 1);
        }
    }
}

// ---------------- kernel 3: scatter (fused per-block scan) ----------------
__global__ void __launch_bounds__(256) k_scatter() {
    __shared__ int s_off[NGRP + 1];
    int tid = threadIdx.x;
    if (tid == 0) {
        int acc = 0;
        #pragma unroll
        for (int i = 0; i < NGRP; i++) { s_off[i] = acc; acc += g_cnt[i]; }
        s_off[NGRP] = acc;
    }
    __syncthreads();
    if (blockIdx.x == 0 && tid <= NGRP) g_off[tid] = s_off[tid];
    int p = blockIdx.x * 256 + tid;
    if (p >= NPAIR) return;
    if (p < NPAIR_R) {
        int t = p / TOPK, k = p % TOPK;
        int e = g_idx[p];
        int pos = s_off[e] + atomicAdd(&g_fill[e], 1);
        g_ptok[pos] = t;
        g_pw  [pos] = g_wk[p];
        g_pos[t * 8 + k] = pos;
    } else {
        int q = p - NPAIR_R;
        int j = q / T_TOK, t = q % T_TOK;
        int pos = s_off[ER + j] + t;
        g_ptok[pos] = t;
        g_pw  [pos] = 1.0f;
        g_pos[t * 8 + TOPK + j] = pos;
    }
}

// ================= GEMM core (round-7): BM=256, BN=128, BK=64, 512 thr =====
__device__ __forceinline__ void mma_chunk(uint32_t aA, uint32_t aB,
                                          float acc[2][8][4],
                                          int warp_m, int warp_n, int lane) {
    int sel = lane >> 3, li = lane & 7;
    int arow = (sel & 1) * 8 + li;
    int acol = (sel >> 1) * 4;
    int brow = (sel & 1) * 8 + li;
    int bn   = (sel >> 1) * 8;
    #pragma unroll
    for (int ks = 0; ks < 4; ks++) {
        uint32_t a[2][4];
        #pragma unroll
        for (int s = 0; s < 2; s++) {
            uint32_t addr = aA + (uint32_t)(((warp_m * 32 + s * 16 + arow) * AST
                                             + ks * 8 + acol) * 4);
            ldsm4(a[s][0], a[s][1], a[s][2], a[s][3], addr);
        }
        #pragma unroll
        for (int p = 0; p < 4; p++) {
            uint32_t b0, b1, b2, b3;
            uint32_t addr = aB + (uint32_t)((ks * 16 + brow) * (BST * 4)
                                            + (warp_n * 64 + p * 16 + bn) * 2);
            ldsm4t(b0, b1, b2, b3, addr);
            #pragma unroll
            for (int s = 0; s < 2; s++) {
                mma_bf16(acc[s][2 * p],     a[s][0], a[s][1], a[s][2], a[s][3], b0, b1);
                mma_bf16(acc[s][2 * p + 1], a[s][0], a[s][1], a[s][2], a[s][3], b2, b3);
            }
        }
    }
}

__device__ __forceinline__ void ldB(const float* __restrict__ W, int ldb, int kk,
                                    int nb, int tid, float4 f[4]) {
    const float* p = W + (size_t)(kk + (tid >> 3)) * ldb + nb + (tid & 7) * 16;
    f[0] = *(const float4*)p;
    f[1] = *(const float4*)(p + 4);
    f[2] = *(const float4*)(p + 8);
    f[3] = *(const float4*)(p + 12);
}
__device__ __forceinline__ void stB(uint32_t* Bbase, int tid, const float4 f[4]) {
    uint32_t* d = Bbase + (tid >> 3) * BST + (tid & 7) * 8;
    *(uint4*)d = make_uint4(pk(f[0].x, f[0].y), pk(f[0].z, f[0].w),
                            pk(f[1].x, f[1].y), pk(f[1].z, f[1].w));
    *(uint4*)(d + 4) = make_uint4(pk(f[2].x, f[2].y), pk(f[2].z, f[2].w),
                                  pk(f[3].x, f[3].y), pk(f[3].z, f[3].w));
}

// ---------------- kernel 4: grouped GEMM1 h = gather(xnb) @ W1[e] + b1 ------
__global__ void __launch_bounds__(512, 1)
k_gemm1(const float* __restrict__ rW1, const float* __restrict__ sW1,
        const float* __restrict__ rb1, const float* __restrict__ sb1) {
    extern __shared__ uint8_t dyn[];
    uint32_t* Bb = (uint32_t*)(dyn + BOFF);
    const uint32_t** sArow = (const uint32_t**)(dyn + XOFF);
    uint32_t saA = cvta(dyn), saB = cvta(Bb);
    int grp = blockIdx.z;
    int start = g_off[grp], cnt = g_off[grp + 1] - start;
    if ((int)blockIdx.x * BMG >= cnt) return;
    const float* W  = (grp < ER) ? rW1 + (size_t)grp * DM * HM
                                 : sW1 + (size_t)(grp - ER) * DM * HM;
    const float* bv = (grp < ER) ? rb1 + (size_t)grp * HM
                                 : sb1 + (size_t)(grp - ER) * HM;
    int nb = blockIdx.y * BNG;
    int tid = threadIdx.x, lane = tid & 31, wid = tid >> 5;
    int warp_m = wid >> 1, warp_n = wid & 1;
    int amf = tid >> 1, ahalf = (tid & 1) * 16;

    for (int mt = blockIdx.x; mt * BMG < cnt; mt += gridDim.x) {
        int m0 = mt * BMG;
        int rem = cnt - m0; if (rem > BMG) rem = BMG;
        bool active = (warp_m * 32 < rem);
        __syncthreads();
        if (tid < BMG)
            sArow[tid] = (tid < rem)
                ? g_xnb + (size_t)g_ptok[start + m0 + tid] * (DM / 2) : g_xnb;
        __syncthreads();
        float acc[2][8][4];
        #pragma unroll
        for (int s = 0; s < 2; s++)
            #pragma unroll
            for (int n = 0; n < 8; n++)
                #pragma unroll
                for (int j = 0; j < 4; j++) acc[s][n][j] = 0.f;
        {
            float4 f[4];
            ldB(W, HM, 0, nb, tid, f);
            stB(Bb, tid, f);
            CPA4(saA + (uint32_t)((amf * AST + ahalf) * 4), sArow[amf] + ahalf);
            CPC(); CPW();
        }
        __syncthreads();
        int buf = 0;
        for (int c = 0; c < DM / BK; c++) {
            float4 f[4];
            bool pre = (c + 1 < DM / BK);
            if (pre) {
                ldB(W, HM, (c + 1) * BK, nb, tid, f);
                CPA4(saA + (buf ^ 1) * ABUF_BYTES + (uint32_t)((amf * AST + ahalf) * 4),
                     sArow[amf] + (c + 1) * 32 + ahalf);
                CPC();
            }
            if (active)
                mma_chunk(saA + buf * ABUF_BYTES, saB + buf * BBUF_BYTES,
                          acc, warp_m, warp_n, lane);
            if (pre) stB(Bb + (buf ^ 1) * BBUFW, tid, f);
            CPW();
            __syncthreads();
            buf ^= 1;
        }
        if (active) {
            #pragma unroll
            for (int s = 0; s < 2; s++) {
                int mrow = warp_m * 32 + s * 16 + (lane >> 2);
                #pragma unroll
                for (int nt = 0; nt < 8; nt++) {
                    int col = nb + warp_n * 64 + nt * 8 + (lane & 3) * 2;
                    float2 bb = *(const float2*)&bv[col];
                    if (mrow < rem) {
                        size_t p = (size_t)(start + m0 + mrow);
                        g_hb[(p * HM + col) >> 1] =
                            pk(acc[s][nt][0] + bb.x, acc[s][nt][1] + bb.y);
                    }
                    if (mrow + 8 < rem) {
                        size_t p = (size_t)(start + m0 + mrow + 8);
                        g_hb[(p * HM + col) >> 1] =
                            pk(acc[s][nt][2] + bb.x, acc[s][nt][3] + bb.y);
                    }
                }
            }
        }
    }
}

// ---------------- kernel 5: gate  g = silu(h @ Wg) * h ----------------
__global__ void __launch_bounds__(512, 1)
k_gate(const float* __restrict__ rWg, const float* __restrict__ sWg) {
    extern __shared__ uint8_t dyn[];
    uint32_t* Bb = (uint32_t*)(dyn + BOFF);
    uint32_t saA = cvta(dyn), saB = cvta(Bb);
    int p0 = blockIdx.x * BMG;
    const float* W = (p0 < NPAIR_R) ? rWg : sWg;
    int nb = blockIdx.y * BNG;
    int tid = threadIdx.x, lane = tid & 31, wid = tid >> 5;
    int warp_m = wid >> 1, warp_n = wid & 1;
    int amf = tid >> 1, ahalf = (tid & 1) * 16;
    const uint32_t* arow = g_hb + (size_t)(p0 + amf) * (HM / 2);

    float acc[2][8][4];
    #pragma unroll
    for (int s = 0; s < 2; s++)
        #pragma unroll
        for (int n = 0; n < 8; n++)
            #pragma unroll
            for (int j = 0; j < 4; j++) acc[s][n][j] = 0.f;
    {
        float4 f[4];
        ldB(W, HM, 0, nb, tid, f);
        stB(Bb, tid, f);
        CPA4(saA + (uint32_t)((amf * AST + ahalf) * 4), arow + ahalf);
        CPC(); CPW();
    }
    __syncthreads();
    int buf = 0;
    for (int c = 0; c < HM / BK; c++) {
        float4 f[4];
        bool pre = (c + 1 < HM / BK);
        if (pre) {
            ldB(W, HM, (c + 1) * BK, nb, tid, f);
            CPA4(saA + (buf ^ 1) * ABUF_BYTES + (uint32_t)((amf * AST + ahalf) * 4),
                 arow + (c + 1) * 32 + ahalf);
            CPC();
        }
        mma_chunk(saA + buf * ABUF_BYTES, saB + buf * BBUF_BYTES,
                  acc, warp_m, warp_n, lane);
        if (pre) stB(Bb + (buf ^ 1) * BBUFW, tid, f);
        CPW();
        __syncthreads();
        buf ^= 1;
    }
    #pragma unroll
    for (int s = 0; s < 2; s++) {
        int mrow = warp_m * 32 + s * 16 + (lane >> 2);
        #pragma unroll
        for (int nt = 0; nt < 8; nt++) {
            int col = nb + warp_n * 64 + nt * 8 + (lane & 3) * 2;
            #pragma unroll
            for (int hh = 0; hh < 2; hh++) {
                size_t p = (size_t)(p0 + mrow + hh * 8);
                size_t idx = (p * HM + col) >> 1;
                uint32_t hu = g_hb[idx];
                float h0 = __uint_as_float(hu << 16);
                float h1 = __uint_as_float(hu & 0xffff0000u);
                float v0 = acc[s][nt][hh * 2 + 0];
                float v1 = acc[s][nt][hh * 2 + 1];
                float r0 = (v0 / (1.f + __expf(-v0))) * h0;
                float r1 = (v1 / (1.f + __expf(-v1))) * h1;
                g_gb[idx] = pk(r0, r1);
            }
        }
    }
}

// ---------------- kernel 6: grouped GEMM2 po = (g @ W2[e] + b2) * w ----------
__global__ void __launch_bounds__(512, 1)
k_gemm2(const float* __restrict__ rW2, const float* __restrict__ sW2,
        const float* __restrict__ rb2, const float* __restrict__ sb2) {
    extern __shared__ uint8_t dyn[];
    uint32_t* Bb = (uint32_t*)(dyn + BOFF);
    float* sPw = (float*)(dyn + XOFF);
    uint32_t saA = cvta(dyn), saB = cvta(Bb);
    int grp = blockIdx.z;
    int start = g_off[grp], cnt = g_off[grp + 1] - start;
    if ((int)blockIdx.x * BMG >= cnt) return;
    const float* W  = (grp < ER) ? rW2 + (size_t)grp * HM * DM
                                 : sW2 + (size_t)(grp - ER) * HM * DM;
    const float* bv = (grp < ER) ? rb2 + (size_t)grp * DM
                                 : sb2 + (size_t)(grp - ER) * DM;
    int nb = blockIdx.y * BNG;
    int tid = threadIdx.x, lane = tid & 31, wid = tid >> 5;
    int warp_m = wid >> 1, warp_n = wid & 1;
    int amf = tid >> 1, ahalf = (tid & 1) * 16;

    for (int mt = blockIdx.x; mt * BMG < cnt; mt += gridDim.x) {
        int m0 = mt * BMG;
        int rem = cnt - m0; if (rem > BMG) rem = BMG;
        bool active = (warp_m * 32 < rem);
        __syncthreads();
        if (tid < BMG) sPw[tid] = (tid < rem) ? g_pw[start + m0 + tid] : 0.f;
        __syncthreads();
        int ar = amf < rem ? amf : (rem - 1);
        const uint32_t* arow = g_gb + (size_t)(start + m0 + ar) * (HM / 2);
        float acc[2][8][4];
        #pragma unroll
        for (int s = 0; s < 2; s++)
            #pragma unroll
            for (int n = 0; n < 8; n++)
                #pragma unroll
                for (int j = 0; j < 4; j++) acc[s][n][j] = 0.f;
        {
            float4 f[4];
            ldB(W, DM, 0, nb, tid, f);
            stB(Bb, tid, f);
            CPA4(saA + (uint32_t)((amf * AST + ahalf) * 4), arow + ahalf);
            CPC(); CPW();
        }
        __syncthreads();
        int buf = 0;
        for (int c = 0; c < HM / BK; c++) {
            float4 f[4];
            bool pre = (c + 1 < HM / BK);
            if (pre) {
                ldB(W, DM, (c + 1) * BK, nb, tid, f);
                CPA4(saA + (buf ^ 1) * ABUF_BYTES + (uint32_t)((amf * AST + ahalf) * 4),
                     arow + (c + 1) * 32 + ahalf);
                CPC();
            }
            if (active)
                mma_chunk(saA + buf * ABUF_BYTES, saB + buf * BBUF_BYTES,
                          acc, warp_m, warp_n, lane);
            if (pre) stB(Bb + (buf ^ 1) * BBUFW, tid, f);
            CPW();
            __syncthreads();
            buf ^= 1;
        }
        if (active) {
            #pragma unroll
            for (int s = 0; s < 2; s++) {
                int mrow = warp_m * 32 + s * 16 + (lane >> 2);
                #pragma unroll
                for (int nt = 0; nt < 8; nt++) {
                    int col = nb + warp_n * 64 + nt * 8 + (lane & 3) * 2;
                    float2 bb = *(const float2*)&bv[col];
                    if (mrow < rem) {
                        size_t p = (size_t)(start + m0 + mrow);
                        float w = sPw[mrow];
                        *(float2*)&g_po[p * DM + col] =
                            make_float2((acc[s][nt][0] + bb.x) * w,
                                        (acc[s][nt][1] + bb.y) * w);
                    }
                    if (mrow + 8 < rem) {
                        size_t p = (size_t)(start + m0 + mrow + 8);
                        float w = sPw[mrow + 8];
                        *(float2*)&g_po[p * DM + col] =
                            make_float2((acc[s][nt][2] + bb.x) * w,
                                        (acc[s][nt][3] + bb.y) * w);
                    }
                }
            }
        }
    }
}

// ---------------- kernel 7: per-token reduce (+residual x) ----------------
__global__ void __launch_bounds__(256) k_reduce(const float* __restrict__ x,
                                                float* __restrict__ out) {
    int t = blockIdx.x, tid = threadIdx.x;
    __shared__ int pos[8];
    if (tid < 8) pos[tid] = g_pos[t * 8 + tid];
    __syncthreads();
    size_t d0 = (size_t)tid * 4;
    float4 s = *(const float4*)&x[(size_t)t * DM + d0];   // residual
    #pragma unroll
    for (int j = 0; j < 8; j++) {
        float4 v = *(const float4*)&g_po[(size_t)pos[j] * DM + d0];
        s.x += v.x; s.y += v.y; s.z += v.z; s.w += v.w;
    }
    *(float4*)&out[(size_t)t * DM + d0] = s;
}

// ---------------- launcher ----------------
extern "C" void kernel_launch(void* const* d_in, const int* in_sizes, int n_in,
                              void* d_out, int out_size) {
    const float* x      = (const float*)d_in[0];
    const float* norm_w = (const float*)d_in[1];
    const float* Wr     = (const float*)d_in[2];
    const float* sW1    = (const float*)d_in[3];
    const float* sb1    = (const float*)d_in[4];
    const float* sW2    = (const float*)d_in[5];
    const float* sb2    = (const float*)d_in[6];
    const float* sWg    = (const float*)d_in[7];
    const float* rW1    = (const float*)d_in[8];
    const float* rb1    = (const float*)d_in[9];
    const float* rW2    = (const float*)d_in[10];
    const float* rb2    = (const float*)d_in[11];
    const float* rWg    = (const float*)d_in[12];
    const float* bias   = (const float*)d_in[13];
    float* out = (float*)d_out;

    cudaFuncSetAttribute(k_gemm1, cudaFuncAttributeMaxDynamicSharedMemorySize, DSMEM);
    cudaFuncSetAttribute(k_gate,  cudaFuncAttributeMaxDynamicSharedMemorySize, DSMEM);
    cudaFuncSetAttribute(k_gemm2, cudaFuncAttributeMaxDynamicSharedMemorySize, DSMEM);

    k_rmsnorm<<<T_TOK, 256>>>(x, norm_w);
    k_route<<<T_TOK / RT, 256>>>(Wr, bias);
    k_scatter<<<(NPAIR + 255) / 256, 256>>>();
    k_gemm1<<<dim3(8, HM / BNG, NGRP), 512, DSMEM>>>(rW1, sW1, rb1, sb1);
    k_gate<<<dim3(NPAIR / BMG, HM / BNG), 512, DSMEM>>>(rWg, sWg);
    k_gemm2<<<dim3(8, DM / BNG, NGRP), 512, DSMEM>>>(rW2, sW2, rb2, sb2);
    k_reduce<<<T_TOK, 256>>>(x, out);
}

// round 14
// speedup vs baseline: 1.4933x; 1.0199x over previous
#include <cuda_runtime.h>
#include <math.h>
#include <stdint.h>

// ---------------- problem constants ----------------
#define T_TOK   2048
#define DM      1024
#define HM      512
#define ER      64
#define TOPK    6
#define ES      2
#define NGRP    (ER + ES)
#define NPAIR_R (T_TOK * TOPK)
#define NPAIR   (NPAIR_R + T_TOK * ES)
#define EPSR    1.1920929e-07f
#define NSM     148

// ---------------- GEMM tile config (measured optimum) ----------------
#define BMG   256
#define BNG   128
#define BK    64
#define AST   36
#define BST   68
#define ABUF_BYTES (BMG * AST * 4)
#define BBUF_BYTES (BK * BST * 4)
#define BBUFW (BK * BST)
#define BOFF  (2 * ABUF_BYTES)
#define XOFF  (BOFF + 2 * BBUF_BYTES)
#define DSMEM (XOFF + 2048)

// job counts: gemm1 = 64*4 routed + 2*8*4 shared = 320; gemm2 = 64*8 + 2*8*8 = 640
#define NJOB1 320
#define NJOB2 640

// ---------------- device scratch ----------------
__device__ float    g_xn [T_TOK * DM];
__device__ uint32_t g_xnb[T_TOK * DM / 2];
__device__ int      g_idx[T_TOK * TOPK];
__device__ float    g_wk [T_TOK * TOPK];
__device__ int      g_cnt[NGRP];
__device__ int      g_off[NGRP + 1];
__device__ int      g_fill[ER];
__device__ int      g_q1, g_q2;                   // job queues
__device__ int      g_ptok[NPAIR];
__device__ float    g_pw  [NPAIR];
__device__ int      g_pos [T_TOK * 8];
__device__ uint32_t g_hb  [(size_t)NPAIR * HM / 2];
__device__ uint32_t g_gb  [(size_t)NPAIR * HM / 2];
__device__ float    g_po  [(size_t)NPAIR * DM];

// ---------------- PTX helpers ----------------
__device__ __forceinline__ uint32_t pk(float lo, float hi) {
    uint32_t r;
    asm("cvt.rn.bf16x2.f32 %0, %1, %2;" : "=r"(r) : "f"(hi), "f"(lo));
    return r;
}
__device__ __forceinline__ uint32_t cvta(const void* p) {
    return (uint32_t)__cvta_generic_to_shared(p);
}
__device__ __forceinline__ void mma_bf16(float* c, uint32_t a0, uint32_t a1,
                                         uint32_t a2, uint32_t a3,
                                         uint32_t b0, uint32_t b1) {
    asm volatile(
        "mma.sync.aligned.m16n8k16.row.col.f32.bf16.bf16.f32 "
        "{%0,%1,%2,%3}, {%4,%5,%6,%7}, {%8,%9}, {%0,%1,%2,%3};\n"
        : "+f"(c[0]), "+f"(c[1]), "+f"(c[2]), "+f"(c[3])
        : "r"(a0), "r"(a1), "r"(a2), "r"(a3), "r"(b0), "r"(b1));
}
__device__ __forceinline__ void ldsm4(uint32_t& r0, uint32_t& r1, uint32_t& r2,
                                      uint32_t& r3, uint32_t a) {
    asm volatile("ldmatrix.sync.aligned.m8n8.x4.shared.b16 {%0,%1,%2,%3}, [%4];"
                 : "=r"(r0), "=r"(r1), "=r"(r2), "=r"(r3) : "r"(a));
}
__device__ __forceinline__ void ldsm4t(uint32_t& r0, uint32_t& r1, uint32_t& r2,
                                       uint32_t& r3, uint32_t a) {
    asm volatile("ldmatrix.sync.aligned.m8n8.x4.trans.shared.b16 {%0,%1,%2,%3}, [%4];"
                 : "=r"(r0), "=r"(r1), "=r"(r2), "=r"(r3) : "r"(a));
}
// .ca: keep L1 caching (r10 .cg regressed; r12 deeper pipeline regressed)
#define CPA(dst, src) \
    asm volatile("cp.async.ca.shared.global [%0], [%1], 16;" \
                 :: "r"(dst), "l"(src) : "memory")
#define CPC() asm volatile("cp.async.commit_group;" ::: "memory")
#define CPW() asm volatile("cp.async.wait_group 0;" ::: "memory")
#define CPA4(dstv, srcv) do { \
    uint32_t _d = (dstv); const uint32_t* _s = (srcv); \
    CPA(_d, _s); CPA(_d + 16, _s + 4); CPA(_d + 32, _s + 8); CPA(_d + 48, _s + 12); \
} while (0)

// ---------------- kernel 1: RMSNorm (+counter/queue reset) ----------------
__global__ void __launch_bounds__(256) k_rmsnorm(const float* __restrict__ x,
                                                 const float* __restrict__ nw) {
    int t = blockIdx.x, tid = threadIdx.x;
    if (blockIdx.x == 0) {
        if (tid < NGRP) g_cnt[tid] = (tid < ER) ? 0 : T_TOK;
        if (tid >= 128 && tid < 128 + ER) g_fill[tid - 128] = 0;
        if (tid == 254) g_q1 = 0;
        if (tid == 255) g_q2 = 0;
    }
    const float4* xr = (const float4*)(x + (size_t)t * DM);
    float4 a = xr[tid];
    float s = a.x * a.x + a.y * a.y + a.z * a.z + a.w * a.w;
    #pragma unroll
    for (int o = 16; o; o >>= 1) s += __shfl_xor_sync(0xffffffffu, s, o);
    __shared__ float ws[8];
    __shared__ float s_scale;
    if ((tid & 31) == 0) ws[tid >> 5] = s;
    __syncthreads();
    if (tid == 0) {
        float tot = 0.f;
        #pragma unroll
        for (int i = 0; i < 8; i++) tot += ws[i];
        s_scale = rsqrtf(tot / (float)DM + EPSR);
    }
    __syncthreads();
    float sc = s_scale;
    float4 w4 = ((const float4*)nw)[tid];
    float4 r;
    r.x = a.x * sc * w4.x; r.y = a.y * sc * w4.y;
    r.z = a.z * sc * w4.z; r.w = a.w * sc * w4.w;
    ((float4*)g_xn)[(size_t)t * 256 + tid] = r;
    ((uint2*)g_xnb)[(size_t)t * 256 + tid] = make_uint2(pk(r.x, r.y), pk(r.z, r.w));
}

// ---------------- kernel 2: router — 16-token tiles + fused top-6 ----------
#define RT 16
__global__ void __launch_bounds__(256) k_route(const float* __restrict__ Wr,
                                               const float* __restrict__ bias) {
    __shared__ float As[32][17];
    __shared__ float Bs[32][68];
    __shared__ float sraw[RT][68];
    int t0 = blockIdx.x * RT;
    int tid = threadIdx.x;
    int ty = tid >> 4, tx = tid & 15;
    float acc[4] = {0.f, 0.f, 0.f, 0.f};
    int la_t = tid & 15, la_k = (tid >> 4) * 4;
    int lb_e = tid & 63, lb_k = (tid >> 6) * 8;
    for (int kk = 0; kk < DM; kk += 32) {
        if (tid < 128) {
            float4 v = *(const float4*)(g_xn + (size_t)(t0 + la_t) * DM + kk + la_k);
            As[la_k + 0][la_t] = v.x; As[la_k + 1][la_t] = v.y;
            As[la_k + 2][la_t] = v.z; As[la_k + 3][la_t] = v.w;
        }
        {
            const float* wp = Wr + (size_t)lb_e * DM + kk + lb_k;
            float4 v0 = *(const float4*)wp;
            float4 v1 = *(const float4*)(wp + 4);
            Bs[lb_k + 0][lb_e] = v0.x; Bs[lb_k + 1][lb_e] = v0.y;
            Bs[lb_k + 2][lb_e] = v0.z; Bs[lb_k + 3][lb_e] = v0.w;
            Bs[lb_k + 4][lb_e] = v1.x; Bs[lb_k + 5][lb_e] = v1.y;
            Bs[lb_k + 6][lb_e] = v1.z; Bs[lb_k + 7][lb_e] = v1.w;
        }
        __syncthreads();
        #pragma unroll
        for (int k = 0; k < 32; k++) {
            float a = As[k][ty];
            float4 b = *(const float4*)&Bs[k][tx * 4];
            acc[0] += a * b.x; acc[1] += a * b.y;
            acc[2] += a * b.z; acc[3] += a * b.w;
        }
        __syncthreads();
    }
    #pragma unroll
    for (int j = 0; j < 4; j++) sraw[ty][tx * 4 + j] = acc[j];
    __syncthreads();
    int lane = tid & 31, wid = tid >> 5;
    float b0 = bias[lane], b1 = bias[lane + 32];
    #pragma unroll
    for (int q = 0; q < 2; q++) {
        int lt = wid * 2 + q;
        int t = t0 + lt;
        float r0 = sraw[lt][lane];
        float r1 = sraw[lt][lane + 32];
        float a0 = r0 + b0;
        float a1 = r1 + b1;
        float sum = 0.f;
        int   sel_e[TOPK];
        float sel_r[TOPK];
        #pragma unroll
        for (int k = 0; k < TOPK; k++) {
            float v; int e;
            if (a0 >= a1) { v = a0; e = lane; } else { v = a1; e = lane + 32; }
            #pragma unroll
            for (int o = 16; o; o >>= 1) {
                float ov = __shfl_xor_sync(0xffffffffu, v, o);
                int   oe = __shfl_xor_sync(0xffffffffu, e, o);
                if (ov > v || (ov == v && oe < e)) { v = ov; e = oe; }
            }
            if (e == lane)      a0 = -1e30f;
            if (e == lane + 32) a1 = -1e30f;
            float ra = __shfl_sync(0xffffffffu, r0, e & 31);
            float rb = __shfl_sync(0xffffffffu, r1, e & 31);
            float rs = (e < 32) ? ra : rb;
            sel_e[k] = e; sel_r[k] = rs; sum += rs;
        }
        float inv = 1.f / sum;
        if (lane < TOPK) {
            g_idx[t * TOPK + lane] = sel_e[lane];
            g_wk [t * TOPK + lane] = sel_r[lane] * inv;
            atomicAdd(&g_cnt[sel_e[lane]], 1);
        }
    }
}

// ---------------- kernel 3: scatter (fused per-block scan) ----------------
__global__ void __launch_bounds__(256) k_scatter() {
    __shared__ int s_off[NGRP + 1];
    int tid = threadIdx.x;
    if (tid == 0) {
        int acc = 0;
        #pragma unroll
        for (int i = 0; i < NGRP; i++) { s_off[i] = acc; acc += g_cnt[i]; }
        s_off[NGRP] = acc;
    }
    __syncthreads();
    if (blockIdx.x == 0 && tid <= NGRP) g_off[tid] = s_off[tid];
    int p = blockIdx.x * 256 + tid;
    if (p >= NPAIR) return;
    if (p < NPAIR_R) {
        int t = p / TOPK, k = p % TOPK;
        int e = g_idx[p];
        int pos = s_off[e] + atomicAdd(&g_fill[e], 1);
        g_ptok[pos] = t;
        g_pw  [pos] = g_wk[p];
        g_pos[t * 8 + k] = pos;
    } else {
        int q = p - NPAIR_R;
        int j = q / T_TOK, t = q % T_TOK;
        int pos = s_off[ER + j] + t;
        g_ptok[pos] = t;
        g_pw  [pos] = 1.0f;
        g_pos[t * 8 + TOPK + j] = pos;
    }
}

// ================= GEMM core: BM=256, BN=128, BK=64, 512 thr ================
__device__ __forceinline__ void mma_chunk(uint32_t aA, uint32_t aB,
                                          float acc[2][8][4],
                                          int warp_m, int warp_n, int lane) {
    int sel = lane >> 3, li = lane & 7;
    int arow = (sel & 1) * 8 + li;
    int acol = (sel >> 1) * 4;
    int brow = (sel & 1) * 8 + li;
    int bn   = (sel >> 1) * 8;
    #pragma unroll
    for (int ks = 0; ks < 4; ks++) {
        uint32_t a[2][4];
        #pragma unroll
        for (int s = 0; s < 2; s++) {
            uint32_t addr = aA + (uint32_t)(((warp_m * 32 + s * 16 + arow) * AST
                                             + ks * 8 + acol) * 4);
            ldsm4(a[s][0], a[s][1], a[s][2], a[s][3], addr);
        }
        #pragma unroll
        for (int p = 0; p < 4; p++) {
            uint32_t b0, b1, b2, b3;
            uint32_t addr = aB + (uint32_t)((ks * 16 + brow) * (BST * 4)
                                            + (warp_n * 64 + p * 16 + bn) * 2);
            ldsm4t(b0, b1, b2, b3, addr);
            #pragma unroll
            for (int s = 0; s < 2; s++) {
                mma_bf16(acc[s][2 * p],     a[s][0], a[s][1], a[s][2], a[s][3], b0, b1);
                mma_bf16(acc[s][2 * p + 1], a[s][0], a[s][1], a[s][2], a[s][3], b2, b3);
            }
        }
    }
}

__device__ __forceinline__ void ldB(const float* __restrict__ W, int ldb, int kk,
                                    int nb, int tid, float4 f[4]) {
    const float* p = W + (size_t)(kk + (tid >> 3)) * ldb + nb + (tid & 7) * 16;
    f[0] = *(const float4*)p;
    f[1] = *(const float4*)(p + 4);
    f[2] = *(const float4*)(p + 8);
    f[3] = *(const float4*)(p + 12);
}
__device__ __forceinline__ void stB(uint32_t* Bbase, int tid, const float4 f[4]) {
    uint32_t* d = Bbase + (tid >> 3) * BST + (tid & 7) * 8;
    *(uint4*)d = make_uint4(pk(f[0].x, f[0].y), pk(f[0].z, f[0].w),
                            pk(f[1].x, f[1].y), pk(f[1].z, f[1].w));
    *(uint4*)(d + 4) = make_uint4(pk(f[2].x, f[2].y), pk(f[2].z, f[2].w),
                                  pk(f[3].x, f[3].y), pk(f[3].z, f[3].w));
}

// ---------------- kernel 4: persistent grouped GEMM1 (work-stealing) --------
__global__ void __launch_bounds__(512, 1)
k_gemm1(const float* __restrict__ rW1, const float* __restrict__ sW1,
        const float* __restrict__ rb1, const float* __restrict__ sb1) {
    extern __shared__ uint8_t dyn[];
    uint32_t* Bb = (uint32_t*)(dyn + BOFF);
    const uint32_t** sArow = (const uint32_t**)(dyn + XOFF);
    __shared__ int s_job;
    uint32_t saA = cvta(dyn), saB = cvta(Bb);
    int tid = threadIdx.x, lane = tid & 31, wid = tid >> 5;
    int warp_m = wid >> 1, warp_n = wid & 1;
    int amf = tid >> 1, ahalf = (tid & 1) * 16;

    for (;;) {
        __syncthreads();
        if (tid == 0) s_job = atomicAdd(&g_q1, 1);
        __syncthreads();
        int job = s_job;
        if (job >= NJOB1) break;
        int grp, nb, m_begin, m_end;
        if (job < 256) {                       // routed: (grp, ntile)
            grp = job >> 2; nb = (job & 3) * BNG;
            m_begin = 0; m_end = g_off[grp + 1] - g_off[grp];
        } else {                               // shared: (grp, mtile, ntile)
            int id2 = job - 256;
            grp = ER + (id2 >> 5);
            int rest = id2 & 31;
            nb = (rest & 3) * BNG;
            m_begin = (rest >> 2) * BMG;
            m_end = m_begin + BMG;
        }
        int start = g_off[grp];
        const float* W  = (grp < ER) ? rW1 + (size_t)grp * DM * HM
                                     : sW1 + (size_t)(grp - ER) * DM * HM;
        const float* bv = (grp < ER) ? rb1 + (size_t)grp * HM
                                     : sb1 + (size_t)(grp - ER) * HM;
        for (int m0 = m_begin; m0 < m_end; m0 += BMG) {
            int rem = m_end - m0; if (rem > BMG) rem = BMG;
            bool active = (warp_m * 32 < rem);
            if (tid < BMG)
                sArow[tid] = (tid < rem)
                    ? g_xnb + (size_t)g_ptok[start + m0 + tid] * (DM / 2) : g_xnb;
            __syncthreads();
            float acc[2][8][4];
            #pragma unroll
            for (int s = 0; s < 2; s++)
                #pragma unroll
                for (int n = 0; n < 8; n++)
                    #pragma unroll
                    for (int j = 0; j < 4; j++) acc[s][n][j] = 0.f;
            {
                float4 f[4];
                ldB(W, HM, 0, nb, tid, f);
                stB(Bb, tid, f);
                CPA4(saA + (uint32_t)((amf * AST + ahalf) * 4), sArow[amf] + ahalf);
                CPC(); CPW();
            }
            __syncthreads();
            int buf = 0;
            for (int c = 0; c < DM / BK; c++) {
                float4 f[4];
                bool pre = (c + 1 < DM / BK);
                if (pre) {
                    ldB(W, HM, (c + 1) * BK, nb, tid, f);
                    CPA4(saA + (buf ^ 1) * ABUF_BYTES + (uint32_t)((amf * AST + ahalf) * 4),
                         sArow[amf] + (c + 1) * 32 + ahalf);
                    CPC();
                }
                if (active)
                    mma_chunk(saA + buf * ABUF_BYTES, saB + buf * BBUF_BYTES,
                              acc, warp_m, warp_n, lane);
                if (pre) stB(Bb + (buf ^ 1) * BBUFW, tid, f);
                CPW();
                __syncthreads();
                buf ^= 1;
            }
            if (active) {
                #pragma unroll
                for (int s = 0; s < 2; s++) {
                    int mrow = warp_m * 32 + s * 16 + (lane >> 2);
                    #pragma unroll
                    for (int nt = 0; nt < 8; nt++) {
                        int col = nb + warp_n * 64 + nt * 8 + (lane & 3) * 2;
                        float2 bb = *(const float2*)&bv[col];
                        if (mrow < rem) {
                            size_t p = (size_t)(start + m0 + mrow);
                            g_hb[(p * HM + col) >> 1] =
                                pk(acc[s][nt][0] + bb.x, acc[s][nt][1] + bb.y);
                        }
                        if (mrow + 8 < rem) {
                            size_t p = (size_t)(start + m0 + mrow + 8);
                            g_hb[(p * HM + col) >> 1] =
                                pk(acc[s][nt][2] + bb.x, acc[s][nt][3] + bb.y);
                        }
                    }
                }
            }
            __syncthreads();
        }
    }
}

// ---------------- kernel 5: gate  g = silu(h @ Wg) * h ----------------
__global__ void __launch_bounds__(512, 1)
k_gate(const float* __restrict__ rWg, const float* __restrict__ sWg) {
    extern __shared__ uint8_t dyn[];
    uint32_t* Bb = (uint32_t*)(dyn + BOFF);
    uint32_t saA = cvta(dyn), saB = cvta(Bb);
    int p0 = blockIdx.x * BMG;
    const float* W = (p0 < NPAIR_R) ? rWg : sWg;
    int nb = blockIdx.y * BNG;
    int tid = threadIdx.x, lane = tid & 31, wid = tid >> 5;
    int warp_m = wid >> 1, warp_n = wid & 1;
    int amf = tid >> 1, ahalf = (tid & 1) * 16;
    const uint32_t* arow = g_hb + (size_t)(p0 + amf) * (HM / 2);

    float acc[2][8][4];
    #pragma unroll
    for (int s = 0; s < 2; s++)
        #pragma unroll
        for (int n = 0; n < 8; n++)
            #pragma unroll
            for (int j = 0; j < 4; j++) acc[s][n][j] = 0.f;
    {
        float4 f[4];
        ldB(W, HM, 0, nb, tid, f);
        stB(Bb, tid, f);
        CPA4(saA + (uint32_t)((amf * AST + ahalf) * 4), arow + ahalf);
        CPC(); CPW();
    }
    __syncthreads();
    int buf = 0;
    for (int c = 0; c < HM / BK; c++) {
        float4 f[4];
        bool pre = (c + 1 < HM / BK);
        if (pre) {
            ldB(W, HM, (c + 1) * BK, nb, tid, f);
            CPA4(saA + (buf ^ 1) * ABUF_BYTES + (uint32_t)((amf * AST + ahalf) * 4),
                 arow + (c + 1) * 32 + ahalf);
            CPC();
        }
        mma_chunk(saA + buf * ABUF_BYTES, saB + buf * BBUF_BYTES,
                  acc, warp_m, warp_n, lane);
        if (pre) stB(Bb + (buf ^ 1) * BBUFW, tid, f);
        CPW();
        __syncthreads();
        buf ^= 1;
    }
    #pragma unroll
    for (int s = 0; s < 2; s++) {
        int mrow = warp_m * 32 + s * 16 + (lane >> 2);
        #pragma unroll
        for (int nt = 0; nt < 8; nt++) {
            int col = nb + warp_n * 64 + nt * 8 + (lane & 3) * 2;
            #pragma unroll
            for (int hh = 0; hh < 2; hh++) {
                size_t p = (size_t)(p0 + mrow + hh * 8);
                size_t idx = (p * HM + col) >> 1;
                uint32_t hu = g_hb[idx];
                float h0 = __uint_as_float(hu << 16);
                float h1 = __uint_as_float(hu & 0xffff0000u);
                float v0 = acc[s][nt][hh * 2 + 0];
                float v1 = acc[s][nt][hh * 2 + 1];
                float r0 = (v0 / (1.f + __expf(-v0))) * h0;
                float r1 = (v1 / (1.f + __expf(-v1))) * h1;
                g_gb[idx] = pk(r0, r1);
            }
        }
    }
}

// ---------------- kernel 6: persistent grouped GEMM2 (work-stealing) --------
__global__ void __launch_bounds__(512, 1)
k_gemm2(const float* __restrict__ rW2, const float* __restrict__ sW2,
        const float* __restrict__ rb2, const float* __restrict__ sb2) {
    extern __shared__ uint8_t dyn[];
    uint32_t* Bb = (uint32_t*)(dyn + BOFF);
    float* sPw = (float*)(dyn + XOFF);
    __shared__ int s_job;
    uint32_t saA = cvta(dyn), saB = cvta(Bb);
    int tid = threadIdx.x, lane = tid & 31, wid = tid >> 5;
    int warp_m = wid >> 1, warp_n = wid & 1;
    int amf = tid >> 1, ahalf = (tid & 1) * 16;

    for (;;) {
        __syncthreads();
        if (tid == 0) s_job = atomicAdd(&g_q2, 1);
        __syncthreads();
        int job = s_job;
        if (job >= NJOB2) break;
        int grp, nb, m_begin, m_end;
        if (job < 512) {                       // routed: (grp, ntile)
            grp = job >> 3; nb = (job & 7) * BNG;
            m_begin = 0; m_end = g_off[grp + 1] - g_off[grp];
        } else {                               // shared: (grp, mtile, ntile)
            int id2 = job - 512;
            grp = ER + (id2 >> 6);
            int rest = id2 & 63;
            nb = (rest & 7) * BNG;
            m_begin = (rest >> 3) * BMG;
            m_end = m_begin + BMG;
        }
        int start = g_off[grp];
        const float* W  = (grp < ER) ? rW2 + (size_t)grp * HM * DM
                                     : sW2 + (size_t)(grp - ER) * HM * DM;
        const float* bv = (grp < ER) ? rb2 + (size_t)grp * DM
                                     : sb2 + (size_t)(grp - ER) * DM;
        for (int m0 = m_begin; m0 < m_end; m0 += BMG) {
            int rem = m_end - m0; if (rem > BMG) rem = BMG;
            bool active = (warp_m * 32 < rem);
            if (tid < BMG) sPw[tid] = (tid < rem) ? g_pw[start + m0 + tid] : 0.f;
            __syncthreads();
            int ar = amf < rem ? amf : (rem - 1);
            const uint32_t* arow = g_gb + (size_t)(start + m0 + ar) * (HM / 2);
            float acc[2][8][4];
            #pragma unroll
            for (int s = 0; s < 2; s++)
                #pragma unroll
                for (int n = 0; n < 8; n++)
                    #pragma unroll
                    for (int j = 0; j < 4; j++) acc[s][n][j] = 0.f;
            {
                float4 f[4];
                ldB(W, DM, 0, nb, tid, f);
                stB(Bb, tid, f);
                CPA4(saA + (uint32_t)((amf * AST + ahalf) * 4), arow + ahalf);
                CPC(); CPW();
            }
            __syncthreads();
            int buf = 0;
            for (int c = 0; c < HM / BK; c++) {
                float4 f[4];
                bool pre = (c + 1 < HM / BK);
                if (pre) {
                    ldB(W, DM, (c + 1) * BK, nb, tid, f);
                    CPA4(saA + (buf ^ 1) * ABUF_BYTES + (uint32_t)((amf * AST + ahalf) * 4),
                         arow + (c + 1) * 32 + ahalf);
                    CPC();
                }
                if (active)
                    mma_chunk(saA + buf * ABUF_BYTES, saB + buf * BBUF_BYTES,
                              acc, warp_m, warp_n, lane);
                if (pre) stB(Bb + (buf ^ 1) * BBUFW, tid, f);
                CPW();
                __syncthreads();
                buf ^= 1;
            }
            if (active) {
                #pragma unroll
                for (int s = 0; s < 2; s++) {
                    int mrow = warp_m * 32 + s * 16 + (lane >> 2);
                    #pragma unroll
                    for (int nt = 0; nt < 8; nt++) {
                        int col = nb + warp_n * 64 + nt * 8 + (lane & 3) * 2;
                        float2 bb = *(const float2*)&bv[col];
                        if (mrow < rem) {
                            size_t p = (size_t)(start + m0 + mrow);
                            float w = sPw[mrow];
                            *(float2*)&g_po[p * DM + col] =
                                make_float2((acc[s][nt][0] + bb.x) * w,
                                            (acc[s][nt][1] + bb.y) * w);
                        }
                        if (mrow + 8 < rem) {
                            size_t p = (size_t)(start + m0 + mrow + 8);
                            float w = sPw[mrow + 8];
                            *(float2*)&g_po[p * DM + col] =
                                make_float2((acc[s][nt][2] + bb.x) * w,
                                            (acc[s][nt][3] + bb.y) * w);
                        }
                    }
                }
            }
            __syncthreads();
        }
    }
}

// ---------------- kernel 7: per-token reduce (+residual x) ----------------
__global__ void __launch_bounds__(256) k_reduce(const float* __restrict__ x,
                                                float* __restrict__ out) {
    int t = blockIdx.x, tid = threadIdx.x;
    __shared__ int pos[8];
    if (tid < 8) pos[tid] = g_pos[t * 8 + tid];
    __syncthreads();
    size_t d0 = (size_t)tid * 4;
    float4 s = *(const float4*)&x[(size_t)t * DM + d0];
    #pragma unroll
    for (int j = 0; j < 8; j++) {
        float4 v = *(const float4*)&g_po[(size_t)pos[j] * DM + d0];
        s.x += v.x; s.y += v.y; s.z += v.z; s.w += v.w;
    }
    *(float4*)&out[(size_t)t * DM + d0] = s;
}

// ---------------- launcher ----------------
extern "C" void kernel_launch(void* const* d_in, const int* in_sizes, int n_in,
                              void* d_out, int out_size) {
    const float* x      = (const float*)d_in[0];
    const float* norm_w = (const float*)d_in[1];
    const float* Wr     = (const float*)d_in[2];
    const float* sW1    = (const float*)d_in[3];
    const float* sb1    = (const float*)d_in[4];
    const float* sW2    = (const float*)d_in[5];
    const float* sb2    = (const float*)d_in[6];
    const float* sWg    = (const float*)d_in[7];
    const float* rW1    = (const float*)d_in[8];
    const float* rb1    = (const float*)d_in[9];
    const float* rW2    = (const float*)d_in[10];
    const float* rb2    = (const float*)d_in[11];
    const float* rWg    = (const float*)d_in[12];
    const float* bias   = (const float*)d_in[13];
    float* out = (float*)d_out;

    cudaFuncSetAttribute(k_gemm1, cudaFuncAttributeMaxDynamicSharedMemorySize, DSMEM);
    cudaFuncSetAttribute(k_gate,  cudaFuncAttributeMaxDynamicSharedMemorySize, DSMEM);
    cudaFuncSetAttribute(k_gemm2, cudaFuncAttributeMaxDynamicSharedMemorySize, DSMEM);

    k_rmsnorm<<<T_TOK, 256>>>(x, norm_w);
    k_route<<<T_TOK / RT, 256>>>(Wr, bias);
    k_scatter<<<(NPAIR + 255) / 256, 256>>>();
    k_gemm1<<<NSM, 512, DSMEM>>>(rW1, sW1, rb1, sb1);
    k_gate<<<dim3(NPAIR / BMG, HM / BNG), 512, DSMEM>>>(rWg, sWg);
    k_gemm2<<<NSM, 512, DSMEM>>>(rW2, sW2, rb2, sb2);
    k_reduce<<<T_TOK, 256>>>(x, out);
}

// round 15
// speedup vs baseline: 1.5328x; 1.0264x over previous
#include <cuda_runtime.h>
#include <math.h>
#include <stdint.h>

// ---------------- problem constants ----------------
#define T_TOK   2048
#define DM      1024
#define HM      512
#define ER      64
#define TOPK    6
#define ES      2
#define NGRP    (ER + ES)
#define NPAIR_R (T_TOK * TOPK)
#define NPAIR   (NPAIR_R + T_TOK * ES)
#define EPSR    1.1920929e-07f
#define NSM     148

// ---------------- GEMM tile config (measured optimum) ----------------
#define BMG   256
#define BNG   128
#define BK    64
#define AST   36
#define BST   68
#define ABUF_BYTES (BMG * AST * 4)
#define BBUF_BYTES (BK * BST * 4)
#define BBUFW (BK * BST)
#define BOFF  (2 * ABUF_BYTES)
#define XOFF  (BOFF + 2 * BBUF_BYTES)
#define DSMEM (XOFF + 2048)

// megakernel job layout
#define NJOB1 320                    // gemm1: 64*4 routed + 2*8*4 shared
#define NJOBG 256                    // gate: 64 m-blocks * 4 ntiles
#define NJOB2 640                    // gemm2: 64*8 routed + 2*8*8 shared
#define NJOBS (NJOB1 + NJOBG + NJOB2)
#define NMB   (NPAIR / BMG)          // 64 gate m-blocks

// ---------------- device scratch ----------------
__device__ float    g_xn [T_TOK * DM];
__device__ uint32_t g_xnb[T_TOK * DM / 2];
__device__ int      g_idx[T_TOK * TOPK];
__device__ float    g_wk [T_TOK * TOPK];
__device__ int      g_cnt[NGRP];
__device__ int      g_off[NGRP + 1];
__device__ int      g_fill[ER];
__device__ int      g_q;                    // megakernel job queue
__device__ int      g_c1[NGRP];             // gemm1 completion per group
__device__ int      g_c2[NMB];              // gate completion per m-block
__device__ int      g_ptok[NPAIR];
__device__ float    g_pw  [NPAIR];
__device__ int      g_pos [T_TOK * 8];
__device__ uint32_t g_hb  [(size_t)NPAIR * HM / 2];
__device__ uint32_t g_gb  [(size_t)NPAIR * HM / 2];
__device__ float    g_po  [(size_t)NPAIR * DM];

// ---------------- PTX helpers ----------------
__device__ __forceinline__ uint32_t pk(float lo, float hi) {
    uint32_t r;
    asm("cvt.rn.bf16x2.f32 %0, %1, %2;" : "=r"(r) : "f"(hi), "f"(lo));
    return r;
}
__device__ __forceinline__ uint32_t cvta(const void* p) {
    return (uint32_t)__cvta_generic_to_shared(p);
}
__device__ __forceinline__ void mma_bf16(float* c, uint32_t a0, uint32_t a1,
                                         uint32_t a2, uint32_t a3,
                                         uint32_t b0, uint32_t b1) {
    asm volatile(
        "mma.sync.aligned.m16n8k16.row.col.f32.bf16.bf16.f32 "
        "{%0,%1,%2,%3}, {%4,%5,%6,%7}, {%8,%9}, {%0,%1,%2,%3};\n"
        : "+f"(c[0]), "+f"(c[1]), "+f"(c[2]), "+f"(c[3])
        : "r"(a0), "r"(a1), "r"(a2), "r"(a3), "r"(b0), "r"(b1));
}
__device__ __forceinline__ void ldsm4(uint32_t& r0, uint32_t& r1, uint32_t& r2,
                                      uint32_t& r3, uint32_t a) {
    asm volatile("ldmatrix.sync.aligned.m8n8.x4.shared.b16 {%0,%1,%2,%3}, [%4];"
                 : "=r"(r0), "=r"(r1), "=r"(r2), "=r"(r3) : "r"(a));
}
__device__ __forceinline__ void ldsm4t(uint32_t& r0, uint32_t& r1, uint32_t& r2,
                                       uint32_t& r3, uint32_t a) {
    asm volatile("ldmatrix.sync.aligned.m8n8.x4.trans.shared.b16 {%0,%1,%2,%3}, [%4];"
                 : "=r"(r0), "=r"(r1), "=r"(r2), "=r"(r3) : "r"(a));
}
// .ca: keep L1 caching (r10 .cg regressed; r12 deeper pipeline regressed)
#define CPA(dst, src) \
    asm volatile("cp.async.ca.shared.global [%0], [%1], 16;" \
                 :: "r"(dst), "l"(src) : "memory")
#define CPC() asm volatile("cp.async.commit_group;" ::: "memory")
#define CPW() asm volatile("cp.async.wait_group 0;" ::: "memory")
#define CPA4(dstv, srcv) do { \
    uint32_t _d = (dstv); const uint32_t* _s = (srcv); \
    CPA(_d, _s); CPA(_d + 16, _s + 4); CPA(_d + 32, _s + 8); CPA(_d + 48, _s + 12); \
} while (0)

// ---------------- kernel 1: RMSNorm (+counter/queue reset) ----------------
__global__ void __launch_bounds__(256) k_rmsnorm(const float* __restrict__ x,
                                                 const float* __restrict__ nw) {
    int t = blockIdx.x, tid = threadIdx.x;
    if (blockIdx.x == 0) {
        if (tid < NGRP) { g_cnt[tid] = (tid < ER) ? 0 : T_TOK; g_c1[tid] = 0; }
        if (tid < ER)  g_fill[tid] = 0;
        if (tid < NMB) g_c2[tid] = 0;
        if (tid == 255) g_q = 0;
    }
    const float4* xr = (const float4*)(x + (size_t)t * DM);
    float4 a = xr[tid];
    float s = a.x * a.x + a.y * a.y + a.z * a.z + a.w * a.w;
    #pragma unroll
    for (int o = 16; o; o >>= 1) s += __shfl_xor_sync(0xffffffffu, s, o);
    __shared__ float ws[8];
    __shared__ float s_scale;
    if ((tid & 31) == 0) ws[tid >> 5] = s;
    __syncthreads();
    if (tid == 0) {
        float tot = 0.f;
        #pragma unroll
        for (int i = 0; i < 8; i++) tot += ws[i];
        s_scale = rsqrtf(tot / (float)DM + EPSR);
    }
    __syncthreads();
    float sc = s_scale;
    float4 w4 = ((const float4*)nw)[tid];
    float4 r;
    r.x = a.x * sc * w4.x; r.y = a.y * sc * w4.y;
    r.z = a.z * sc * w4.z; r.w = a.w * sc * w4.w;
    ((float4*)g_xn)[(size_t)t * 256 + tid] = r;
    ((uint2*)g_xnb)[(size_t)t * 256 + tid] = make_uint2(pk(r.x, r.y), pk(r.z, r.w));
}

// ---------------- kernel 2: router — 16-token tiles + fused top-6 ----------
#define RT 16
__global__ void __launch_bounds__(256) k_route(const float* __restrict__ Wr,
                                               const float* __restrict__ bias) {
    __shared__ float As[32][17];
    __shared__ float Bs[32][68];
    __shared__ float sraw[RT][68];
    int t0 = blockIdx.x * RT;
    int tid = threadIdx.x;
    int ty = tid >> 4, tx = tid & 15;
    float acc[4] = {0.f, 0.f, 0.f, 0.f};
    int la_t = tid & 15, la_k = (tid >> 4) * 4;
    int lb_e = tid & 63, lb_k = (tid >> 6) * 8;
    for (int kk = 0; kk < DM; kk += 32) {
        if (tid < 128) {
            float4 v = *(const float4*)(g_xn + (size_t)(t0 + la_t) * DM + kk + la_k);
            As[la_k + 0][la_t] = v.x; As[la_k + 1][la_t] = v.y;
            As[la_k + 2][la_t] = v.z; As[la_k + 3][la_t] = v.w;
        }
        {
            const float* wp = Wr + (size_t)lb_e * DM + kk + lb_k;
            float4 v0 = *(const float4*)wp;
            float4 v1 = *(const float4*)(wp + 4);
            Bs[lb_k + 0][lb_e] = v0.x; Bs[lb_k + 1][lb_e] = v0.y;
            Bs[lb_k + 2][lb_e] = v0.z; Bs[lb_k + 3][lb_e] = v0.w;
            Bs[lb_k + 4][lb_e] = v1.x; Bs[lb_k + 5][lb_e] = v1.y;
            Bs[lb_k + 6][lb_e] = v1.z; Bs[lb_k + 7][lb_e] = v1.w;
        }
        __syncthreads();
        #pragma unroll
        for (int k = 0; k < 32; k++) {
            float a = As[k][ty];
            float4 b = *(const float4*)&Bs[k][tx * 4];
            acc[0] += a * b.x; acc[1] += a * b.y;
            acc[2] += a * b.z; acc[3] += a * b.w;
        }
        __syncthreads();
    }
    #pragma unroll
    for (int j = 0; j < 4; j++) sraw[ty][tx * 4 + j] = acc[j];
    __syncthreads();
    int lane = tid & 31, wid = tid >> 5;
    float b0 = bias[lane], b1 = bias[lane + 32];
    #pragma unroll
    for (int q = 0; q < 2; q++) {
        int lt = wid * 2 + q;
        int t = t0 + lt;
        float r0 = sraw[lt][lane];
        float r1 = sraw[lt][lane + 32];
        float a0 = r0 + b0;
        float a1 = r1 + b1;
        float sum = 0.f;
        int   sel_e[TOPK];
        float sel_r[TOPK];
        #pragma unroll
        for (int k = 0; k < TOPK; k++) {
            float v; int e;
            if (a0 >= a1) { v = a0; e = lane; } else { v = a1; e = lane + 32; }
            #pragma unroll
            for (int o = 16; o; o >>= 1) {
                float ov = __shfl_xor_sync(0xffffffffu, v, o);
                int   oe = __shfl_xor_sync(0xffffffffu, e, o);
                if (ov > v || (ov == v && oe < e)) { v = ov; e = oe; }
            }
            if (e == lane)      a0 = -1e30f;
            if (e == lane + 32) a1 = -1e30f;
            float ra = __shfl_sync(0xffffffffu, r0, e & 31);
            float rb = __shfl_sync(0xffffffffu, r1, e & 31);
            float rs = (e < 32) ? ra : rb;
            sel_e[k] = e; sel_r[k] = rs; sum += rs;
        }
        float inv = 1.f / sum;
        if (lane < TOPK) {
            g_idx[t * TOPK + lane] = sel_e[lane];
            g_wk [t * TOPK + lane] = sel_r[lane] * inv;
            atomicAdd(&g_cnt[sel_e[lane]], 1);
        }
    }
}

// ---------------- kernel 3: scatter (fused per-block scan) ----------------
__global__ void __launch_bounds__(256) k_scatter() {
    __shared__ int s_off[NGRP + 1];
    int tid = threadIdx.x;
    if (tid == 0) {
        int acc = 0;
        #pragma unroll
        for (int i = 0; i < NGRP; i++) { s_off[i] = acc; acc += g_cnt[i]; }
        s_off[NGRP] = acc;
    }
    __syncthreads();
    if (blockIdx.x == 0 && tid <= NGRP) g_off[tid] = s_off[tid];
    int p = blockIdx.x * 256 + tid;
    if (p >= NPAIR) return;
    if (p < NPAIR_R) {
        int t = p / TOPK, k = p % TOPK;
        int e = g_idx[p];
        int pos = s_off[e] + atomicAdd(&g_fill[e], 1);
        g_ptok[pos] = t;
        g_pw  [pos] = g_wk[p];
        g_pos[t * 8 + k] = pos;
    } else {
        int q = p - NPAIR_R;
        int j = q / T_TOK, t = q % T_TOK;
        int pos = s_off[ER + j] + t;
        g_ptok[pos] = t;
        g_pw  [pos] = 1.0f;
        g_pos[t * 8 + TOPK + j] = pos;
    }
}

// ================= GEMM core: BM=256, BN=128, BK=64, 512 thr ================
__device__ __forceinline__ void mma_chunk(uint32_t aA, uint32_t aB,
                                          float acc[2][8][4],
                                          int warp_m, int warp_n, int lane) {
    int sel = lane >> 3, li = lane & 7;
    int arow = (sel & 1) * 8 + li;
    int acol = (sel >> 1) * 4;
    int brow = (sel & 1) * 8 + li;
    int bn   = (sel >> 1) * 8;
    #pragma unroll
    for (int ks = 0; ks < 4; ks++) {
        uint32_t a[2][4];
        #pragma unroll
        for (int s = 0; s < 2; s++) {
            uint32_t addr = aA + (uint32_t)(((warp_m * 32 + s * 16 + arow) * AST
                                             + ks * 8 + acol) * 4);
            ldsm4(a[s][0], a[s][1], a[s][2], a[s][3], addr);
        }
        #pragma unroll
        for (int p = 0; p < 4; p++) {
            uint32_t b0, b1, b2, b3;
            uint32_t addr = aB + (uint32_t)((ks * 16 + brow) * (BST * 4)
                                            + (warp_n * 64 + p * 16 + bn) * 2);
            ldsm4t(b0, b1, b2, b3, addr);
            #pragma unroll
            for (int s = 0; s < 2; s++) {
                mma_bf16(acc[s][2 * p],     a[s][0], a[s][1], a[s][2], a[s][3], b0, b1);
                mma_bf16(acc[s][2 * p + 1], a[s][0], a[s][1], a[s][2], a[s][3], b2, b3);
            }
        }
    }
}

__device__ __forceinline__ void ldB(const float* __restrict__ W, int ldb, int kk,
                                    int nb, int tid, float4 f[4]) {
    const float* p = W + (size_t)(kk + (tid >> 3)) * ldb + nb + (tid & 7) * 16;
    f[0] = *(const float4*)p;
    f[1] = *(const float4*)(p + 4);
    f[2] = *(const float4*)(p + 8);
    f[3] = *(const float4*)(p + 12);
}
__device__ __forceinline__ void stB(uint32_t* Bbase, int tid, const float4 f[4]) {
    uint32_t* d = Bbase + (tid >> 3) * BST + (tid & 7) * 8;
    *(uint4*)d = make_uint4(pk(f[0].x, f[0].y), pk(f[0].z, f[0].w),
                            pk(f[1].x, f[1].y), pk(f[1].z, f[1].w));
    *(uint4*)(d + 4) = make_uint4(pk(f[2].x, f[2].y), pk(f[2].z, f[2].w),
                                  pk(f[3].x, f[3].y), pk(f[3].z, f[3].w));
}

// ---------------- kernel 4: persistent fused GEMM1+gate+GEMM2 ---------------
__global__ void __launch_bounds__(512, 1)
k_moe(const float* __restrict__ rW1, const float* __restrict__ sW1,
      const float* __restrict__ rb1, const float* __restrict__ sb1,
      const float* __restrict__ rWg, const float* __restrict__ sWg,
      const float* __restrict__ rW2, const float* __restrict__ sW2,
      const float* __restrict__ rb2, const float* __restrict__ sb2) {
    extern __shared__ uint8_t dyn[];
    uint32_t* Bb = (uint32_t*)(dyn + BOFF);
    const uint32_t** sArow = (const uint32_t**)(dyn + XOFF);
    float* sPw = (float*)(dyn + XOFF);
    __shared__ int s_job;
    uint32_t saA = cvta(dyn), saB = cvta(Bb);
    int tid = threadIdx.x, lane = tid & 31, wid = tid >> 5;
    int warp_m = wid >> 1, warp_n = wid & 1;
    int amf = tid >> 1, ahalf = (tid & 1) * 16;

    for (;;) {
        __syncthreads();
        if (tid == 0) s_job = atomicAdd(&g_q, 1);
        __syncthreads();
        int job = s_job;
        if (job >= NJOBS) break;

        if (job < NJOB1) {
            // ================= GEMM1 =================
            int grp, nb, m_begin, m_end;
            if (job < 256) {
                grp = job >> 2; nb = (job & 3) * BNG;
                m_begin = 0; m_end = g_off[grp + 1] - g_off[grp];
            } else {
                int id2 = job - 256;
                grp = ER + (id2 >> 5);
                int rest = id2 & 31;
                nb = (rest & 3) * BNG;
                m_begin = (rest >> 2) * BMG;
                m_end = m_begin + BMG;
            }
            int start = g_off[grp];
            const float* W  = (grp < ER) ? rW1 + (size_t)grp * DM * HM
                                         : sW1 + (size_t)(grp - ER) * DM * HM;
            const float* bv = (grp < ER) ? rb1 + (size_t)grp * HM
                                         : sb1 + (size_t)(grp - ER) * HM;
            for (int m0 = m_begin; m0 < m_end; m0 += BMG) {
                int rem = m_end - m0; if (rem > BMG) rem = BMG;
                bool active = (warp_m * 32 < rem);
                if (tid < BMG)
                    sArow[tid] = (tid < rem)
                        ? g_xnb + (size_t)g_ptok[start + m0 + tid] * (DM / 2) : g_xnb;
                __syncthreads();
                float acc[2][8][4];
                #pragma unroll
                for (int s = 0; s < 2; s++)
                    #pragma unroll
                    for (int n = 0; n < 8; n++)
                        #pragma unroll
                        for (int j = 0; j < 4; j++) acc[s][n][j] = 0.f;
                {
                    float4 f[4];
                    ldB(W, HM, 0, nb, tid, f);
                    stB(Bb, tid, f);
                    CPA4(saA + (uint32_t)((amf * AST + ahalf) * 4), sArow[amf] + ahalf);
                    CPC(); CPW();
                }
                __syncthreads();
                int buf = 0;
                for (int c = 0; c < DM / BK; c++) {
                    float4 f[4];
                    bool pre = (c + 1 < DM / BK);
                    if (pre) {
                        ldB(W, HM, (c + 1) * BK, nb, tid, f);
                        CPA4(saA + (buf ^ 1) * ABUF_BYTES + (uint32_t)((amf * AST + ahalf) * 4),
                             sArow[amf] + (c + 1) * 32 + ahalf);
                        CPC();
                    }
                    if (active)
                        mma_chunk(saA + buf * ABUF_BYTES, saB + buf * BBUF_BYTES,
                                  acc, warp_m, warp_n, lane);
                    if (pre) stB(Bb + (buf ^ 1) * BBUFW, tid, f);
                    CPW();
                    __syncthreads();
                    buf ^= 1;
                }
                if (active) {
                    #pragma unroll
                    for (int s = 0; s < 2; s++) {
                        int mrow = warp_m * 32 + s * 16 + (lane >> 2);
                        #pragma unroll
                        for (int nt = 0; nt < 8; nt++) {
                            int col = nb + warp_n * 64 + nt * 8 + (lane & 3) * 2;
                            float2 bb = *(const float2*)&bv[col];
                            if (mrow < rem) {
                                size_t p = (size_t)(start + m0 + mrow);
                                g_hb[(p * HM + col) >> 1] =
                                    pk(acc[s][nt][0] + bb.x, acc[s][nt][1] + bb.y);
                            }
                            if (mrow + 8 < rem) {
                                size_t p = (size_t)(start + m0 + mrow + 8);
                                g_hb[(p * HM + col) >> 1] =
                                    pk(acc[s][nt][2] + bb.x, acc[s][nt][3] + bb.y);
                            }
                        }
                    }
                }
                __syncthreads();
            }
            __threadfence();
            __syncthreads();
            if (tid == 0) atomicAdd(&g_c1[grp], 1);
        } else if (job < NJOB1 + NJOBG) {
            // ================= GATE =================
            int j = job - NJOB1;
            int mb = j >> 2, nt2 = j & 3;
            int p0 = mb * BMG, nb = nt2 * BNG;
            // wait for gemm1 of all experts overlapping this block
            if (tid == 0) {
                int lo = p0, hi = p0 + BMG;
                for (int e = 0; e < NGRP; e++) {
                    if (g_off[e] < hi && g_off[e + 1] > lo) {
                        int tgt = (e < ER) ? 4 : 32;
                        volatile int* c = (volatile int*)&g_c1[e];
                        while (*c < tgt) __nanosleep(64);
                    }
                }
                __threadfence();
            }
            __syncthreads();
            const float* W = (p0 < NPAIR_R) ? rWg : sWg;
            const uint32_t* arow = g_hb + (size_t)(p0 + amf) * (HM / 2);
            float acc[2][8][4];
            #pragma unroll
            for (int s = 0; s < 2; s++)
                #pragma unroll
                for (int n = 0; n < 8; n++)
                    #pragma unroll
                    for (int j2 = 0; j2 < 4; j2++) acc[s][n][j2] = 0.f;
            {
                float4 f[4];
                ldB(W, HM, 0, nb, tid, f);
                stB(Bb, tid, f);
                CPA4(saA + (uint32_t)((amf * AST + ahalf) * 4), arow + ahalf);
                CPC(); CPW();
            }
            __syncthreads();
            int buf = 0;
            for (int c = 0; c < HM / BK; c++) {
                float4 f[4];
                bool pre = (c + 1 < HM / BK);
                if (pre) {
                    ldB(W, HM, (c + 1) * BK, nb, tid, f);
                    CPA4(saA + (buf ^ 1) * ABUF_BYTES + (uint32_t)((amf * AST + ahalf) * 4),
                         arow + (c + 1) * 32 + ahalf);
                    CPC();
                }
                mma_chunk(saA + buf * ABUF_BYTES, saB + buf * BBUF_BYTES,
                          acc, warp_m, warp_n, lane);
                if (pre) stB(Bb + (buf ^ 1) * BBUFW, tid, f);
                CPW();
                __syncthreads();
                buf ^= 1;
            }
            #pragma unroll
            for (int s = 0; s < 2; s++) {
                int mrow = warp_m * 32 + s * 16 + (lane >> 2);
                #pragma unroll
                for (int nt = 0; nt < 8; nt++) {
                    int col = nb + warp_n * 64 + nt * 8 + (lane & 3) * 2;
                    #pragma unroll
                    for (int hh = 0; hh < 2; hh++) {
                        size_t p = (size_t)(p0 + mrow + hh * 8);
                        size_t idx = (p * HM + col) >> 1;
                        uint32_t hu = g_hb[idx];
                        float h0 = __uint_as_float(hu << 16);
                        float h1 = __uint_as_float(hu & 0xffff0000u);
                        float v0 = acc[s][nt][hh * 2 + 0];
                        float v1 = acc[s][nt][hh * 2 + 1];
                        float r0 = (v0 / (1.f + __expf(-v0))) * h0;
                        float r1 = (v1 / (1.f + __expf(-v1))) * h1;
                        g_gb[idx] = pk(r0, r1);
                    }
                }
            }
            __threadfence();
            __syncthreads();
            if (tid == 0) atomicAdd(&g_c2[mb], 1);
        } else {
            // ================= GEMM2 =================
            int j = job - NJOB1 - NJOBG;
            int grp, nb, m_begin, m_end;
            if (j < 512) {
                grp = j >> 3; nb = (j & 7) * BNG;
                m_begin = 0; m_end = g_off[grp + 1] - g_off[grp];
            } else {
                int j2 = j - 512;
                grp = ER + (j2 >> 6);
                int rest = j2 & 63;
                nb = (rest & 7) * BNG;
                m_begin = (rest >> 3) * BMG;
                m_end = m_begin + BMG;
            }
            int start = g_off[grp];
            // wait for gate of all m-blocks overlapping this job's rows
            if (tid == 0) {
                if (m_end > m_begin) {
                    int lo = start + m_begin, hi = start + m_end;
                    int b0 = lo / BMG, b1 = (hi - 1) / BMG;
                    for (int b = b0; b <= b1; b++) {
                        volatile int* c = (volatile int*)&g_c2[b];
                        while (*c < 4) __nanosleep(64);
                    }
                }
                __threadfence();
            }
            __syncthreads();
            const float* W  = (grp < ER) ? rW2 + (size_t)grp * HM * DM
                                         : sW2 + (size_t)(grp - ER) * HM * DM;
            const float* bv = (grp < ER) ? rb2 + (size_t)grp * DM
                                         : sb2 + (size_t)(grp - ER) * DM;
            for (int m0 = m_begin; m0 < m_end; m0 += BMG) {
                int rem = m_end - m0; if (rem > BMG) rem = BMG;
                bool active = (warp_m * 32 < rem);
                if (tid < BMG) sPw[tid] = (tid < rem) ? g_pw[start + m0 + tid] : 0.f;
                __syncthreads();
                int ar = amf < rem ? amf : (rem - 1);
                const uint32_t* arow = g_gb + (size_t)(start + m0 + ar) * (HM / 2);
                float acc[2][8][4];
                #pragma unroll
                for (int s = 0; s < 2; s++)
                    #pragma unroll
                    for (int n = 0; n < 8; n++)
                        #pragma unroll
                        for (int j2 = 0; j2 < 4; j2++) acc[s][n][j2] = 0.f;
                {
                    float4 f[4];
                    ldB(W, DM, 0, nb, tid, f);
                    stB(Bb, tid, f);
                    CPA4(saA + (uint32_t)((amf * AST + ahalf) * 4), arow + ahalf);
                    CPC(); CPW();
                }
                __syncthreads();
                int buf = 0;
                for (int c = 0; c < HM / BK; c++) {
                    float4 f[4];
                    bool pre = (c + 1 < HM / BK);
                    if (pre) {
                        ldB(W, DM, (c + 1) * BK, nb, tid, f);
                        CPA4(saA + (buf ^ 1) * ABUF_BYTES + (uint32_t)((amf * AST + ahalf) * 4),
                             arow + (c + 1) * 32 + ahalf);
                        CPC();
                    }
                    if (active)
                        mma_chunk(saA + buf * ABUF_BYTES, saB + buf * BBUF_BYTES,
                                  acc, warp_m, warp_n, lane);
                    if (pre) stB(Bb + (buf ^ 1) * BBUFW, tid, f);
                    CPW();
                    __syncthreads();
                    buf ^= 1;
                }
                if (active) {
                    #pragma unroll
                    for (int s = 0; s < 2; s++) {
                        int mrow = warp_m * 32 + s * 16 + (lane >> 2);
                        #pragma unroll
                        for (int nt = 0; nt < 8; nt++) {
                            int col = nb + warp_n * 64 + nt * 8 + (lane & 3) * 2;
                            float2 bb = *(const float2*)&bv[col];
                            if (mrow < rem) {
                                size_t p = (size_t)(start + m0 + mrow);
                                float w = sPw[mrow];
                                *(float2*)&g_po[p * DM + col] =
                                    make_float2((acc[s][nt][0] + bb.x) * w,
                                                (acc[s][nt][1] + bb.y) * w);
                            }
                            if (mrow + 8 < rem) {
                                size_t p = (size_t)(start + m0 + mrow + 8);
                                float w = sPw[mrow + 8];
                                *(float2*)&g_po[p * DM + col] =
                                    make_float2((acc[s][nt][2] + bb.x) * w,
                                                (acc[s][nt][3] + bb.y) * w);
                            }
                        }
                    }
                }
                __syncthreads();
            }
        }
    }
}

// ---------------- kernel 5: per-token reduce (+residual x) ----------------
__global__ void __launch_bounds__(256) k_reduce(const float* __restrict__ x,
                                                float* __restrict__ out) {
    int t = blockIdx.x, tid = threadIdx.x;
    __shared__ int pos[8];
    if (tid < 8) pos[tid] = g_pos[t * 8 + tid];
    __syncthreads();
    size_t d0 = (size_t)tid * 4;
    float4 s = *(const float4*)&x[(size_t)t * DM + d0];
    #pragma unroll
    for (int j = 0; j < 8; j++) {
        float4 v = *(const float4*)&g_po[(size_t)pos[j] * DM + d0];
        s.x += v.x; s.y += v.y; s.z += v.z; s.w += v.w;
    }
    *(float4*)&out[(size_t)t * DM + d0] = s;
}

// ---------------- launcher ----------------
extern "C" void kernel_launch(void* const* d_in, const int* in_sizes, int n_in,
                              void* d_out, int out_size) {
    const float* x      = (const float*)d_in[0];
    const float* norm_w = (const float*)d_in[1];
    const float* Wr     = (const float*)d_in[2];
    const float* sW1    = (const float*)d_in[3];
    const float* sb1    = (const float*)d_in[4];
    const float* sW2    = (const float*)d_in[5];
    const float* sb2    = (const float*)d_in[6];
    const float* sWg    = (const float*)d_in[7];
    const float* rW1    = (const float*)d_in[8];
    const float* rb1    = (const float*)d_in[9];
    const float* rW2    = (const float*)d_in[10];
    const float* rb2    = (const float*)d_in[11];
    const float* rWg    = (const float*)d_in[12];
    const float* bias   = (const float*)d_in[13];
    float* out = (float*)d_out;

    cudaFuncSetAttribute(k_moe, cudaFuncAttributeMaxDynamicSharedMemorySize, DSMEM);

    k_rmsnorm<<<T_TOK, 256>>>(x, norm_w);
    k_route<<<T_TOK / RT, 256>>>(Wr, bias);
    k_scatter<<<(NPAIR + 255) / 256, 256>>>();
    k_moe<<<NSM, 512, DSMEM>>>(rW1, sW1, rb1, sb1, rWg, sWg, rW2, sW2, rb2, sb2);
    k_reduce<<<T_TOK, 256>>>(x, out);
}